// round 11
// baseline (speedup 1.0000x reference)
#include <cuda_runtime.h>
#include <cstdint>
#include <math.h>

#define BB   16
#define CIN  64
#define HH   64
#define WW   64
#define HID  128
#define OC4  512   // 4*HID

typedef unsigned long long ull;

// double-buffered h state: [par][b][ic][w]  (row0 never read -> no init needed)
__device__ float g_h[2 * BB * HID * WW];
// monotonic progress flags: [b][rank] (never reset; base read per launch)
__device__ int   g_flag[BB * 8];

// ---- packed fp32x2 helpers (SASS FFMA2 path, PTX-only) ----------------------
__device__ __forceinline__ ull pk2(float a, float b) {
    ull r; asm("mov.b64 %0, {%1,%2};" : "=l"(r) : "f"(a), "f"(b)); return r;
}
__device__ __forceinline__ ull dup2(float a) {
    ull r; asm("mov.b64 %0, {%1,%1};" : "=l"(r) : "f"(a)); return r;
}
__device__ __forceinline__ void ffma2(ull& d, ull a, ull b) {
    asm("fma.rn.f32x2 %0, %1, %2, %0;" : "+l"(d) : "l"(a), "l"(b));
}
__device__ __forceinline__ ull add2(ull a, ull b) {
    ull r; asm("add.rn.f32x2 %0, %1, %2;" : "=l"(r) : "l"(a), "l"(b)); return r;
}
__device__ __forceinline__ float lo32(ull a) {
    float x; asm("{ .reg .b32 t; mov.b64 {%0, t}, %1; }" : "=f"(x) : "l"(a)); return x;
}
__device__ __forceinline__ float hi32(ull a) {
    float x; asm("{ .reg .b32 t; mov.b64 {t, %0}, %1; }" : "=f"(x) : "l"(a)); return x;
}

// ---- fast transcendentals (MUFU path; error ~1e-6, budget 1e-3) -------------
__device__ __forceinline__ float fsig(float x) {
    return __fdividef(1.f, 1.f + __expf(-x));
}
__device__ __forceinline__ float ftanh(float x) {
    x = fminf(fmaxf(x, -15.f), 15.f);      // avoid __expf overflow -> NaN
    float t = __expf(-2.f * x);
    return __fdividef(1.f - t, 1.f + t);
}

// ---- scoped release/acquire flag ops ----------------------------------------
__device__ __forceinline__ void st_release(int* p, int v) {
    asm volatile("st.release.gpu.global.s32 [%0], %1;" :: "l"(p), "r"(v) : "memory");
}
__device__ __forceinline__ int ld_acquire(int* p) {
    int v;
    asm volatile("ld.acquire.gpu.global.s32 %0, [%1];" : "=r"(v) : "l"(p) : "memory");
    return v;
}

// ----------------------------------------------------------------------------
// Fused kernel: input conv + row scan, tap-planar weight layouts.
// 8 CTAs per batch, 256 threads. l = tid&63, wb = tid>>6 (16 w each).
// Wsm[t][ic][64 l] and Wx[tap][cin][64 l]: every weight load is a scalar LDS
// with 4B lane stride -> exactly 1 wavefront (vs 4 for the float4/strided form).
// ----------------------------------------------------------------------------
#define CONV_IC(ic)                                                          \
    do {                                                                     \
        ull w0d = dup2(Wsm[          (ic) * 64 + l]);                        \
        ull w1d = dup2(Wsm[ 8192 +   (ic) * 64 + l]);                        \
        ull w2d = dup2(Wsm[16384 +   (ic) * 64 + l]);                        \
        const float* hrow = &hs[(ic) * 68 + w0];                             \
        ull A[9];                                                            \
        ulonglong2 q0 = *(const ulonglong2*)(hrow);                          \
        ulonglong2 q1 = *(const ulonglong2*)(hrow + 4);                      \
        ulonglong2 q2 = *(const ulonglong2*)(hrow + 8);                      \
        ulonglong2 q3 = *(const ulonglong2*)(hrow + 12);                     \
        A[0] = q0.x; A[1] = q0.y; A[2] = q1.x; A[3] = q1.y;                  \
        A[4] = q2.x; A[5] = q2.y; A[6] = q3.x; A[7] = q3.y;                  \
        A[8] = *(const ull*)(hrow + 16);                                     \
        _Pragma("unroll")                                                    \
        for (int k = 0; k < 8; k++) {                                        \
            ffma2(acc[k], A[k],     w0d);                                    \
            ffma2(acc[k], A[k + 1], w2d);                                    \
            ffma2(T[k],   A[k],     w1d);                                    \
        }                                                                    \
        ffma2(T[8], A[8], w1d);                                              \
    } while (0)

#define CONV_X(cin)                                                          \
    do {                                                                     \
        ull wAd = dup2(Wx[       (cin) * 64 + l]);                           \
        ull wBd = dup2(Wx[4096 + (cin) * 64 + l]);                           \
        const float* xrow = &xs[(cin) * 68 + w0];                            \
        ull A[9];                                                            \
        ulonglong2 q0 = *(const ulonglong2*)(xrow);                          \
        ulonglong2 q1 = *(const ulonglong2*)(xrow + 4);                      \
        ulonglong2 q2 = *(const ulonglong2*)(xrow + 8);                      \
        ulonglong2 q3 = *(const ulonglong2*)(xrow + 12);                     \
        A[0] = q0.x; A[1] = q0.y; A[2] = q1.x; A[3] = q1.y;                  \
        A[4] = q2.x; A[5] = q2.y; A[6] = q3.x; A[7] = q3.y;                  \
        A[8] = *(const ull*)(xrow + 16);                                     \
        _Pragma("unroll")                                                    \
        for (int k = 0; k < 8; k++) {                                        \
            ffma2(acc[k], A[k], wAd);                                        \
            ffma2(T[k],   A[k], wBd);                                        \
        }                                                                    \
        ffma2(T[8], A[8], wBd);                                              \
    } while (0)

__global__ void __launch_bounds__(256)
scan_kernel(const float* __restrict__ x,
            const float* __restrict__ w_is,
            const float* __restrict__ b_is,
            const float* __restrict__ w_ss,
            const float* __restrict__ b_ss,
            float* __restrict__ out)
{
    extern __shared__ float smem[];
    float* Wsm  = smem;                    // [3 t][128 ic][64 l] 24576 floats
    float* Wx   = Wsm + 3 * 128 * 64;      // [2 tap][64 cin][64]  8192 floats
    float* hs   = Wx + 2 * 64 * 64;        // [128 ic][68]         8704 floats
    float* xs   = hs + 128 * 68;           // [64 cin][68]         4352 floats
    float* zbuf = xs + 64 * 68;            // [64 l][64]           4096 floats
    float* cs   = zbuf + 64 * 64;          // [16 hcl][64 w]       1024 floats

    int tid  = threadIdx.x;
    int rank = blockIdx.x & 7;
    int b    = blockIdx.x >> 3;
    int o0   = rank * 16;                  // own ic range [o0, o0+16)

    int* flags = g_flag + b * 8;
    int base = *(volatile int*)(flags + rank);   // own flag: race-free

    // stage recurrent weights, tap-planar: Wsm[t*8192 + ic*64 + l]
    for (int i = tid; i < 3 * 128 * 64; i += 256) {
        int t = i >> 13, r = i & 8191;
        int ic = r >> 6, lx = r & 63;
        int ocgx = (lx >> 4) * 128 + o0 + (lx & 15);
        Wsm[i] = w_ss[((long)ocgx * 128 + ic) * 3 + t];
    }
    // stage input weights, tap-planar: Wx[tap*4096 + cin*64 + l]
    for (int i = tid; i < 2 * 64 * 64; i += 256) {
        int tap = i >> 12, r = i & 4095;
        int cin = r >> 6, lx = r & 63;
        int ocgx = (lx >> 4) * 128 + o0 + (lx & 15);
        Wx[i] = w_is[(long)ocgx * 192 + cin * 3 + tap];
    }
    // zero hs (row 0: h0 = 0), xs (pads persist), c state
    for (int i = tid; i < 128 * 68; i += 256) hs[i] = 0.f;
    for (int i = tid; i < 64 * 68; i += 256)  xs[i] = 0.f;
    for (int i = tid; i < 16 * 64; i += 256)  cs[i] = 0.f;
    __syncthreads();
    // load x row 0: x[b][cin][0][w]
    {
        const float* xb = x + (long)b * CIN * HH * WW;
        for (int i = tid; i < 1024; i += 256) {       // float4 index
            int cin = i >> 4, wq = (i & 15) * 4;
            float4 v = *(const float4*)&xb[((long)cin * HH + 0) * WW + wq];
            float* d = &xs[cin * 68 + wq + 1];
            d[0] = v.x; d[1] = v.y; d[2] = v.z; d[3] = v.w;
        }
    }
    __syncthreads();

    int l  = tid & 63;        // gate g = l>>4, local hid = l&15
    int wb = tid >> 6;        // 0..3, warp-uniform
    int w0 = wb * 16;
    int ocg = (l >> 4) * 128 + o0 + (l & 15);
    ull bias2 = dup2(b_ss[ocg] + b_is[ocg]);   // both biases folded

    for (int row = 0; row < HH; row++) {
        int par  = row & 1;
        int par1 = par ^ 1;

        // ---- phase A: fused input conv (64 cin) + own-16-ic h-conv ----
        ull acc[8], T[9];
#pragma unroll
        for (int k = 0; k < 8; k++) acc[k] = 0ull;
#pragma unroll
        for (int k = 0; k < 9; k++) T[k] = 0ull;

#pragma unroll 4
        for (int cin = 0; cin < 64; cin++) CONV_X(cin);
#pragma unroll 4
        for (int ic = o0; ic < o0 + 16; ic++) CONV_IC(ic);

        // ---- phase B: wait peers; refill xs(row+1); copy peer h; conv rest --
        if (row > 0) {
            if (tid < 8) {
                while (ld_acquire(flags + tid) < base + row) { }
            }
        }
        __syncthreads();                 // xs/hs reads of phase A complete

        if (row < HH - 1) {              // prefetch next x row (no dependency)
            const float* xb = x + (long)b * CIN * HH * WW;
            for (int i = tid; i < 1024; i += 256) {
                int cin = i >> 4, wq = (i & 15) * 4;
                float4 v = *(const float4*)&xb[((long)cin * HH + row + 1) * WW + wq];
                float* d = &xs[cin * 68 + wq + 1];
                d[0] = v.x; d[1] = v.y; d[2] = v.z; d[3] = v.w;
            }
        }
        if (row > 0) {
            const float4* gh4 = (const float4*)&g_h[((long)par * BB + b) * HID * WW];
            for (int i = tid; i < 112 * 16; i += 256) {
                int icl = i >> 4;
                int ic  = icl + (icl >= o0 ? 16 : 0);
                float4 v = gh4[ic * 16 + (i & 15)];
                float* d = &hs[ic * 68 + (i & 15) * 4 + 1];
                d[0] = v.x; d[1] = v.y; d[2] = v.z; d[3] = v.w;
            }
            __syncthreads();

#pragma unroll 4
            for (int ic = 0; ic < o0; ic++) CONV_IC(ic);
#pragma unroll 4
            for (int ic = o0 + 16; ic < 128; ic++) CONV_IC(ic);
        }

        // combine: acc += bias and shifted odd-tap accumulator
#pragma unroll
        for (int k = 0; k < 8; k++) {
            acc[k] = add2(acc[k], bias2);
            acc[k] = add2(acc[k], pk2(hi32(T[k]), lo32(T[k + 1])));
        }
#pragma unroll
        for (int k = 0; k < 8; k++)
            *(ull*)&zbuf[l * 64 + w0 + 2 * k] = acc[k];
        __syncthreads();

        // ---- phase C: gates (MUFU); write out, own h -> smem + global ----
        float* ghw = &g_h[((long)par1 * BB + b) * HID * WW];
#pragma unroll
        for (int k = 0; k < 4; k++) {
            int idx = tid + k * 256;
            int hcl = idx >> 6, w = idx & 63;
            float zi  = zbuf[(0  + hcl) * 64 + w];
            float zf  = zbuf[(16 + hcl) * 64 + w];
            float zo  = zbuf[(32 + hcl) * 64 + w];
            float zg2 = zbuf[(48 + hcl) * 64 + w];
            float ig = fsig(zi);
            float fg = fsig(zf);
            float og = fsig(zo);
            float gg = ftanh(zg2);
            float c = fg * cs[hcl * 64 + w] + ig * gg;
            cs[hcl * 64 + w] = c;
            float hv2 = og * ftanh(c);
            int ch = o0 + hcl;
            out[(((long)b * HID + ch) * HH + row) * WW + w] = hv2;
            if (row < HH - 1) {
                ghw[ch * WW + w] = hv2;            // publish to peers
                hs[ch * 68 + w + 1] = hv2;         // own copy for next phase A
            }
        }

        if (row < HH - 1) {
            __syncthreads();                       // all writes happen-before tid0
            if (tid == 0) st_release(flags + rank, base + row + 1);
        }
    }
}

// ----------------------------------------------------------------------------
extern "C" void kernel_launch(void* const* d_in, const int* in_sizes, int n_in,
                              void* d_out, int out_size)
{
    (void)in_sizes; (void)n_in; (void)out_size;
    const float* x    = (const float*)d_in[0];
    const float* w_is = (const float*)d_in[1];
    const float* b_is = (const float*)d_in[2];
    const float* w_ss = (const float*)d_in[3];
    const float* b_ss = (const float*)d_in[4];
    float* out = (float*)d_out;

    const int scan_smem =
        (3 * 128 * 64 + 2 * 64 * 64 + 128 * 68 + 64 * 68 + 64 * 64 + 16 * 64) * 4; // 203776 B

    cudaFuncSetAttribute(scan_kernel, cudaFuncAttributeMaxDynamicSharedMemorySize, scan_smem);

    scan_kernel<<<BB * 8, 256, scan_smem>>>(x, w_is, b_is, w_ss, b_ss, out);
}

// round 12
// speedup vs baseline: 1.0246x; 1.0246x over previous
#include <cuda_runtime.h>
#include <cstdint>
#include <math.h>

#define BB   16
#define CIN  64
#define HH   64
#define WW   64
#define HID  128
#define OC4  512   // 4*HID

typedef unsigned long long ull;

// double-buffered h state: [par][b][ic][w]  (row0 never read -> no init needed)
__device__ float g_h[2 * BB * HID * WW];
// monotonic progress flags: [b][rank] (never reset; base read per launch)
__device__ int   g_flag[BB * 8];

// ---- packed fp32x2 helpers (SASS FFMA2 path, PTX-only) ----------------------
__device__ __forceinline__ ull pk2(float a, float b) {
    ull r; asm("mov.b64 %0, {%1,%2};" : "=l"(r) : "f"(a), "f"(b)); return r;
}
__device__ __forceinline__ ull dup2(float a) {
    ull r; asm("mov.b64 %0, {%1,%1};" : "=l"(r) : "f"(a)); return r;
}
__device__ __forceinline__ void ffma2(ull& d, ull a, ull b) {
    asm("fma.rn.f32x2 %0, %1, %2, %0;" : "+l"(d) : "l"(a), "l"(b));
}
__device__ __forceinline__ ull add2(ull a, ull b) {
    ull r; asm("add.rn.f32x2 %0, %1, %2;" : "=l"(r) : "l"(a), "l"(b)); return r;
}
__device__ __forceinline__ float lo32(ull a) {
    float x; asm("{ .reg .b32 t; mov.b64 {%0, t}, %1; }" : "=f"(x) : "l"(a)); return x;
}
__device__ __forceinline__ float hi32(ull a) {
    float x; asm("{ .reg .b32 t; mov.b64 {t, %0}, %1; }" : "=f"(x) : "l"(a)); return x;
}

// ---- fast transcendentals ----------------------------------------------------
__device__ __forceinline__ float frcp(float x) {          // MUFU.RCP
    float r; asm("rcp.approx.f32 %0, %1;" : "=f"(r) : "f"(x)); return r;
}
__device__ __forceinline__ float clamp15(float x) {
    return fminf(fmaxf(x, -15.f), 15.f);
}

// ---- scoped release/acquire flag ops ----------------------------------------
__device__ __forceinline__ void st_release(int* p, int v) {
    asm volatile("st.release.gpu.global.s32 [%0], %1;" :: "l"(p), "r"(v) : "memory");
}
__device__ __forceinline__ int ld_acquire(int* p) {
    int v;
    asm volatile("ld.acquire.gpu.global.s32 %0, [%1];" : "=r"(v) : "l"(p) : "memory");
    return v;
}

// ----------------------------------------------------------------------------
// Fused kernel: input conv + row scan (R10 structure, proven 1119us).
// 8 CTAs per batch, 256 threads. l = tid&63, wb = tid>>6 (16 w each).
// Wq float4: .xyz = w_ss taps, .w slot ic encodes w_is[cin=ic>>1][tap=ic&1].
// Gate phase: batch-reciprocal gates, 7 MUFU/elem (was 10).
// ----------------------------------------------------------------------------
#define CONV_IC(ic)                                                          \
    do {                                                                     \
        const float4 wv = *(const float4*)&Wq[(ic) * 256 + l * 4];           \
        ull w0d = dup2(wv.x), w1d = dup2(wv.y), w2d = dup2(wv.z);            \
        const float* hrow = &hs[(ic) * 68 + w0];                             \
        ull A[9];                                                            \
        ulonglong2 q0 = *(const ulonglong2*)(hrow);                          \
        ulonglong2 q1 = *(const ulonglong2*)(hrow + 4);                      \
        ulonglong2 q2 = *(const ulonglong2*)(hrow + 8);                      \
        ulonglong2 q3 = *(const ulonglong2*)(hrow + 12);                     \
        A[0] = q0.x; A[1] = q0.y; A[2] = q1.x; A[3] = q1.y;                  \
        A[4] = q2.x; A[5] = q2.y; A[6] = q3.x; A[7] = q3.y;                  \
        A[8] = *(const ull*)(hrow + 16);                                     \
        _Pragma("unroll")                                                    \
        for (int k = 0; k < 8; k++) {                                        \
            ffma2(acc[k], A[k],     w0d);                                    \
            ffma2(acc[k], A[k + 1], w2d);                                    \
            ffma2(T[k],   A[k],     w1d);                                    \
        }                                                                    \
        ffma2(T[8], A[8], w1d);                                              \
    } while (0)

#define CONV_X(cin)                                                          \
    do {                                                                     \
        ull wAd = dup2(Wq[(2 * (cin))     * 256 + l * 4 + 3]);               \
        ull wBd = dup2(Wq[(2 * (cin) + 1) * 256 + l * 4 + 3]);               \
        const float* xrow = &xs[(cin) * 68 + w0];                            \
        ull A[9];                                                            \
        ulonglong2 q0 = *(const ulonglong2*)(xrow);                          \
        ulonglong2 q1 = *(const ulonglong2*)(xrow + 4);                      \
        ulonglong2 q2 = *(const ulonglong2*)(xrow + 8);                      \
        ulonglong2 q3 = *(const ulonglong2*)(xrow + 12);                     \
        A[0] = q0.x; A[1] = q0.y; A[2] = q1.x; A[3] = q1.y;                  \
        A[4] = q2.x; A[5] = q2.y; A[6] = q3.x; A[7] = q3.y;                  \
        A[8] = *(const ull*)(xrow + 16);                                     \
        _Pragma("unroll")                                                    \
        for (int k = 0; k < 8; k++) {                                        \
            ffma2(acc[k], A[k], wAd);                                        \
            ffma2(T[k],   A[k], wBd);                                        \
        }                                                                    \
        ffma2(T[8], A[8], wBd);                                              \
    } while (0)

__global__ void __launch_bounds__(256)
scan_kernel(const float* __restrict__ x,
            const float* __restrict__ w_is,
            const float* __restrict__ b_is,
            const float* __restrict__ w_ss,
            const float* __restrict__ b_ss,
            float* __restrict__ out)
{
    extern __shared__ float smem[];
    float* Wq   = smem;                    // [ic][64 l][4]      32768 floats
    float* hs   = Wq + 128 * 64 * 4;       // [128 ic][68]        8704 floats
    float* xs   = hs + 128 * 68;           // [64 cin][68]        4352 floats
    float* zbuf = xs + 64 * 68;            // [64 l][64]          4096 floats
    float* cs   = zbuf + 64 * 64;          // [16 hcl][64 w]      1024 floats

    int tid  = threadIdx.x;
    int rank = blockIdx.x & 7;
    int b    = blockIdx.x >> 3;
    int o0   = rank * 16;                  // own ic range [o0, o0+16)

    int* flags = g_flag + b * 8;
    int base = *(volatile int*)(flags + rank);   // own flag: race-free

    // stage packed weights: Wq[ic][l] = (w_ss t0,t1,t2, w_is[ic>>1][ic&1])
    for (int i = tid; i < 128 * 64 * 4; i += 256) {
        int t = i & 3, lx = (i >> 2) & 63, ic = i >> 8;
        int ocgx = (lx >> 4) * 128 + o0 + (lx & 15);
        float v;
        if (t < 3) v = w_ss[((long)ocgx * 128 + ic) * 3 + t];
        else       v = w_is[(long)ocgx * 192 + (ic >> 1) * 3 + (ic & 1)];
        Wq[i] = v;
    }
    // zero hs (row 0: h0 = 0), xs (pads persist), c state
    for (int i = tid; i < 128 * 68; i += 256) hs[i] = 0.f;
    for (int i = tid; i < 64 * 68; i += 256)  xs[i] = 0.f;
    for (int i = tid; i < 16 * 64; i += 256)  cs[i] = 0.f;
    __syncthreads();
    // load x row 0: x[b][cin][0][w]
    {
        const float* xb = x + (long)b * CIN * HH * WW;
        for (int i = tid; i < 1024; i += 256) {       // float4 index
            int cin = i >> 4, wq = (i & 15) * 4;
            float4 v = *(const float4*)&xb[((long)cin * HH + 0) * WW + wq];
            float* d = &xs[cin * 68 + wq + 1];
            d[0] = v.x; d[1] = v.y; d[2] = v.z; d[3] = v.w;
        }
    }
    __syncthreads();

    int l  = tid & 63;        // gate g = l>>4, local hid = l&15
    int wb = tid >> 6;        // 0..3, warp-uniform
    int w0 = wb * 16;
    int ocg = (l >> 4) * 128 + o0 + (l & 15);
    ull bias2 = dup2(b_ss[ocg] + b_is[ocg]);   // both biases folded

    for (int row = 0; row < HH; row++) {
        int par  = row & 1;
        int par1 = par ^ 1;

        // ---- phase A: fused input conv (64 cin) + own-16-ic h-conv ----
        ull acc[8], T[9];
#pragma unroll
        for (int k = 0; k < 8; k++) acc[k] = 0ull;
#pragma unroll
        for (int k = 0; k < 9; k++) T[k] = 0ull;

#pragma unroll 4
        for (int cin = 0; cin < 64; cin++) CONV_X(cin);
#pragma unroll 4
        for (int ic = o0; ic < o0 + 16; ic++) CONV_IC(ic);

        // ---- phase B: wait peers; refill xs(row+1); copy peer h; conv rest --
        if (row > 0) {
            if (tid < 8) {
                while (ld_acquire(flags + tid) < base + row) { }
            }
        }
        __syncthreads();                 // xs/hs reads of phase A complete

        if (row < HH - 1) {              // prefetch next x row (no dependency)
            const float* xb = x + (long)b * CIN * HH * WW;
            for (int i = tid; i < 1024; i += 256) {
                int cin = i >> 4, wq = (i & 15) * 4;
                float4 v = *(const float4*)&xb[((long)cin * HH + row + 1) * WW + wq];
                float* d = &xs[cin * 68 + wq + 1];
                d[0] = v.x; d[1] = v.y; d[2] = v.z; d[3] = v.w;
            }
        }
        if (row > 0) {
            const float4* gh4 = (const float4*)&g_h[((long)par * BB + b) * HID * WW];
            for (int i = tid; i < 112 * 16; i += 256) {
                int icl = i >> 4;
                int ic  = icl + (icl >= o0 ? 16 : 0);
                float4 v = gh4[ic * 16 + (i & 15)];
                float* d = &hs[ic * 68 + (i & 15) * 4 + 1];
                d[0] = v.x; d[1] = v.y; d[2] = v.z; d[3] = v.w;
            }
            __syncthreads();

#pragma unroll 4
            for (int ic = 0; ic < o0; ic++) CONV_IC(ic);
#pragma unroll 4
            for (int ic = o0 + 16; ic < 128; ic++) CONV_IC(ic);
        }

        // combine: acc += bias and shifted odd-tap accumulator
#pragma unroll
        for (int k = 0; k < 8; k++) {
            acc[k] = add2(acc[k], bias2);
            acc[k] = add2(acc[k], pk2(hi32(T[k]), lo32(T[k + 1])));
        }
#pragma unroll
        for (int k = 0; k < 8; k++)
            *(ull*)&zbuf[l * 64 + w0 + 2 * k] = acc[k];
        __syncthreads();

        // ---- phase C: gates via batch reciprocal (7 MUFU/elem) ----
        float* ghw = &g_h[((long)par1 * BB + b) * HID * WW];
#pragma unroll
        for (int k = 0; k < 4; k++) {
            int idx = tid + k * 256;
            int hcl = idx >> 6, w = idx & 63;
            float zi  = clamp15(zbuf[(0  + hcl) * 64 + w]);
            float zf  = clamp15(zbuf[(16 + hcl) * 64 + w]);
            float zo  = clamp15(zbuf[(32 + hcl) * 64 + w]);
            float zg2 = clamp15(zbuf[(48 + hcl) * 64 + w]);
            // denominators: d1..d3 = 1+e^-z (sigmoids), d4 = 1+e^-2zg (tanh g)
            float e1 = __expf(-zi);
            float e2 = __expf(-zf);
            float e3 = __expf(-zo);
            float e4 = __expf(-2.f * zg2);
            float d1 = 1.f + e1, d2 = 1.f + e2, d3 = 1.f + e3, d4 = 1.f + e4;
            // batch reciprocal: one RCP recovers all four 1/di
            float p12 = d1 * d2, p34 = d3 * d4;
            float r   = frcp(p12 * p34);
            float rp34 = r * p34, rp12 = r * p12;
            float ig = rp34 * d2;            // 1/d1
            float fg = rp34 * d1;            // 1/d2
            float og = rp12 * d4;            // 1/d3
            float gg = (1.f - e4) * (rp12 * d3);   // tanh(zg) = (1-e4)/d4
            float c = fg * cs[hcl * 64 + w] + ig * gg;
            cs[hcl * 64 + w] = c;
            float e5 = __expf(-2.f * clamp15(c));
            float hv2 = og * (1.f - e5) * frcp(1.f + e5);
            int ch = o0 + hcl;
            out[(((long)b * HID + ch) * HH + row) * WW + w] = hv2;
            if (row < HH - 1) {
                ghw[ch * WW + w] = hv2;            // publish to peers
                hs[ch * 68 + w + 1] = hv2;         // own copy for next phase A
            }
        }

        if (row < HH - 1) {
            __syncthreads();                       // all writes happen-before tid0
            if (tid == 0) st_release(flags + rank, base + row + 1);
        }
    }
}

// ----------------------------------------------------------------------------
extern "C" void kernel_launch(void* const* d_in, const int* in_sizes, int n_in,
                              void* d_out, int out_size)
{
    (void)in_sizes; (void)n_in; (void)out_size;
    const float* x    = (const float*)d_in[0];
    const float* w_is = (const float*)d_in[1];
    const float* b_is = (const float*)d_in[2];
    const float* w_ss = (const float*)d_in[3];
    const float* b_ss = (const float*)d_in[4];
    float* out = (float*)d_out;

    const int scan_smem = (128 * 64 * 4 + 128 * 68 + 64 * 68 + 64 * 64 + 16 * 64) * 4; // 203776 B

    cudaFuncSetAttribute(scan_kernel, cudaFuncAttributeMaxDynamicSharedMemorySize, scan_smem);

    scan_kernel<<<BB * 8, 256, scan_smem>>>(x, w_is, b_is, w_ss, b_ss, out);
}

// round 13
// speedup vs baseline: 1.1135x; 1.0867x over previous
#include <cuda_runtime.h>
#include <cstdint>
#include <math.h>

#define BB   16
#define CIN  64
#define HH   64
#define WW   64
#define HID  128
#define OC4  512   // 4*HID

typedef unsigned long long ull;

// double-buffered h state: [par][b][ic][w]  (row0 never read -> no init needed)
__device__ float g_h[2 * BB * HID * WW];
// monotonic progress flags: [b][rank] (never reset; base read per launch)
__device__ int   g_flag[BB * 8];

// ---- packed fp32x2 helpers (SASS FFMA2 path, PTX-only) ----------------------
__device__ __forceinline__ ull pk2(float a, float b) {
    ull r; asm("mov.b64 %0, {%1,%2};" : "=l"(r) : "f"(a), "f"(b)); return r;
}
__device__ __forceinline__ ull dup2(float a) {
    ull r; asm("mov.b64 %0, {%1,%1};" : "=l"(r) : "f"(a)); return r;
}
__device__ __forceinline__ void ffma2(ull& d, ull a, ull b) {
    asm("fma.rn.f32x2 %0, %1, %2, %0;" : "+l"(d) : "l"(a), "l"(b));
}
__device__ __forceinline__ ull add2(ull a, ull b) {
    ull r; asm("add.rn.f32x2 %0, %1, %2;" : "=l"(r) : "l"(a), "l"(b)); return r;
}
__device__ __forceinline__ float lo32(ull a) {
    float x; asm("{ .reg .b32 t; mov.b64 {%0, t}, %1; }" : "=f"(x) : "l"(a)); return x;
}
__device__ __forceinline__ float hi32(ull a) {
    float x; asm("{ .reg .b32 t; mov.b64 {t, %0}, %1; }" : "=f"(x) : "l"(a)); return x;
}

// ---- fast transcendentals ----------------------------------------------------
__device__ __forceinline__ float frcp(float x) {          // MUFU.RCP
    float r; asm("rcp.approx.f32 %0, %1;" : "=f"(r) : "f"(x)); return r;
}
__device__ __forceinline__ float clamp15(float x) {
    return fminf(fmaxf(x, -15.f), 15.f);
}

// ---- scoped release/acquire flag ops ----------------------------------------
__device__ __forceinline__ void st_release(int* p, int v) {
    asm volatile("st.release.gpu.global.s32 [%0], %1;" :: "l"(p), "r"(v) : "memory");
}
__device__ __forceinline__ int ld_acquire(int* p) {
    int v;
    asm volatile("ld.acquire.gpu.global.s32 %0, [%1];" : "=r"(v) : "l"(p) : "memory");
    return v;
}

#define BARS(id, cnt) \
    asm volatile("bar.sync %0, %1;" :: "r"(id), "r"(cnt) : "memory")

// ----------------------------------------------------------------------------
// Warp-specialized fused kernel. 512 threads: warps 0-7 compute, 8-15 IO.
// Compute: conv (R12 macros unchanged) + gates. IO: flag spin, peer-h copy,
// xs prefetch, h publish + flag release — all off the compute critical path.
// ----------------------------------------------------------------------------
#define CONV_IC(ic)                                                          \
    do {                                                                     \
        const float4 wv = *(const float4*)&Wq[(ic) * 256 + l * 4];           \
        ull w0d = dup2(wv.x), w1d = dup2(wv.y), w2d = dup2(wv.z);            \
        const float* hrow = &hs[(ic) * 68 + w0];                             \
        ull A[9];                                                            \
        ulonglong2 q0 = *(const ulonglong2*)(hrow);                          \
        ulonglong2 q1 = *(const ulonglong2*)(hrow + 4);                      \
        ulonglong2 q2 = *(const ulonglong2*)(hrow + 8);                      \
        ulonglong2 q3 = *(const ulonglong2*)(hrow + 12);                     \
        A[0] = q0.x; A[1] = q0.y; A[2] = q1.x; A[3] = q1.y;                  \
        A[4] = q2.x; A[5] = q2.y; A[6] = q3.x; A[7] = q3.y;                  \
        A[8] = *(const ull*)(hrow + 16);                                     \
        _Pragma("unroll")                                                    \
        for (int k = 0; k < 8; k++) {                                        \
            ffma2(acc[k], A[k],     w0d);                                    \
            ffma2(acc[k], A[k + 1], w2d);                                    \
            ffma2(T[k],   A[k],     w1d);                                    \
        }                                                                    \
        ffma2(T[8], A[8], w1d);                                              \
    } while (0)

#define CONV_X(cin)                                                          \
    do {                                                                     \
        ull wAd = dup2(Wq[(2 * (cin))     * 256 + l * 4 + 3]);               \
        ull wBd = dup2(Wq[(2 * (cin) + 1) * 256 + l * 4 + 3]);               \
        const float* xrow = &xs[(cin) * 68 + w0];                            \
        ull A[9];                                                            \
        ulonglong2 q0 = *(const ulonglong2*)(xrow);                          \
        ulonglong2 q1 = *(const ulonglong2*)(xrow + 4);                      \
        ulonglong2 q2 = *(const ulonglong2*)(xrow + 8);                      \
        ulonglong2 q3 = *(const ulonglong2*)(xrow + 12);                     \
        A[0] = q0.x; A[1] = q0.y; A[2] = q1.x; A[3] = q1.y;                  \
        A[4] = q2.x; A[5] = q2.y; A[6] = q3.x; A[7] = q3.y;                  \
        A[8] = *(const ull*)(xrow + 16);                                     \
        _Pragma("unroll")                                                    \
        for (int k = 0; k < 8; k++) {                                        \
            ffma2(acc[k], A[k], wAd);                                        \
            ffma2(T[k],   A[k], wBd);                                        \
        }                                                                    \
        ffma2(T[8], A[8], wBd);                                              \
    } while (0)

__global__ void __launch_bounds__(512)
scan_kernel(const float* __restrict__ x,
            const float* __restrict__ w_is,
            const float* __restrict__ b_is,
            const float* __restrict__ w_ss,
            const float* __restrict__ b_ss,
            float* __restrict__ out)
{
    extern __shared__ float smem[];
    float* Wq   = smem;                    // [ic][64 l][4]      32768 floats
    float* hs   = Wq + 128 * 64 * 4;       // [128 ic][68]        8704 floats
    float* xs   = hs + 128 * 68;           // [64 cin][68]        4352 floats
    float* zbuf = xs + 64 * 68;            // [64 l][64]          4096 floats
    float* cs   = zbuf + 64 * 64;          // [16 hcl][64 w]      1024 floats

    int tid  = threadIdx.x;
    int rank = blockIdx.x & 7;
    int b    = blockIdx.x >> 3;
    int o0   = rank * 16;                  // own ic range [o0, o0+16)

    int* flags = g_flag + b * 8;
    int base = *(volatile int*)(flags + rank);   // own flag: race-free

    // ---- prologue (all 512 threads) ----
    for (int i = tid; i < 128 * 64 * 4; i += 512) {
        int t = i & 3, lx = (i >> 2) & 63, ic = i >> 8;
        int ocgx = (lx >> 4) * 128 + o0 + (lx & 15);
        float v;
        if (t < 3) v = w_ss[((long)ocgx * 128 + ic) * 3 + t];
        else       v = w_is[(long)ocgx * 192 + (ic >> 1) * 3 + (ic & 1)];
        Wq[i] = v;
    }
    for (int i = tid; i < 128 * 68; i += 512) hs[i] = 0.f;
    for (int i = tid; i < 64 * 68; i += 512)  xs[i] = 0.f;
    for (int i = tid; i < 16 * 64; i += 512)  cs[i] = 0.f;
    __syncthreads();
    {   // x row 0
        const float* xb = x + (long)b * CIN * HH * WW;
        for (int i = tid; i < 1024; i += 512) {
            int cin = i >> 4, wq = (i & 15) * 4;
            float4 v = *(const float4*)&xb[((long)cin * HH + 0) * WW + wq];
            float* d = &xs[cin * 68 + wq + 1];
            d[0] = v.x; d[1] = v.y; d[2] = v.z; d[3] = v.w;
        }
    }
    __syncthreads();

    if (tid < 256) {
        // ================= COMPUTE WARPS =================
        int l  = tid & 63;
        int wb = tid >> 6;        // 0..3
        int w0 = wb * 16;
        int ocg = (l >> 4) * 128 + o0 + (l & 15);
        ull bias2 = dup2(b_ss[ocg] + b_is[ocg]);

        for (int row = 0; row < HH; row++) {
            // phase A: x-conv + own h-conv (peer h not needed)
            ull acc[8], T[9];
#pragma unroll
            for (int k = 0; k < 8; k++) acc[k] = 0ull;
#pragma unroll
            for (int k = 0; k < 9; k++) T[k] = 0ull;

#pragma unroll 4
            for (int cin = 0; cin < 64; cin++) CONV_X(cin);
#pragma unroll 4
            for (int ic = o0; ic < o0 + 16; ic++) CONV_IC(ic);

            BARS(1, 512);                    // peer h in smem /\ A done

            if (row > 0) {
#pragma unroll 4
                for (int ic = 0; ic < o0; ic++) CONV_IC(ic);
#pragma unroll 4
                for (int ic = o0 + 16; ic < 128; ic++) CONV_IC(ic);
            }

            BARS(2, 512);                    // B done /\ xs(row+1) staged

#pragma unroll
            for (int k = 0; k < 8; k++) {
                acc[k] = add2(acc[k], bias2);
                acc[k] = add2(acc[k], pk2(hi32(T[k]), lo32(T[k + 1])));
            }
#pragma unroll
            for (int k = 0; k < 8; k++)
                *(ull*)&zbuf[l * 64 + w0 + 2 * k] = acc[k];

            BARS(3, 256);                    // zbuf ready (compute only)

            // gates: write out + own h -> smem only (IO publishes to gmem)
#pragma unroll
            for (int k = 0; k < 4; k++) {
                int idx = tid + k * 256;
                int hcl = idx >> 6, w = idx & 63;
                float zi  = clamp15(zbuf[(0  + hcl) * 64 + w]);
                float zf  = clamp15(zbuf[(16 + hcl) * 64 + w]);
                float zo  = clamp15(zbuf[(32 + hcl) * 64 + w]);
                float zg2 = clamp15(zbuf[(48 + hcl) * 64 + w]);
                float e1 = __expf(-zi);
                float e2 = __expf(-zf);
                float e3 = __expf(-zo);
                float e4 = __expf(-2.f * zg2);
                float d1 = 1.f + e1, d2 = 1.f + e2, d3 = 1.f + e3, d4 = 1.f + e4;
                float p12 = d1 * d2, p34 = d3 * d4;
                float r   = frcp(p12 * p34);
                float rp34 = r * p34, rp12 = r * p12;
                float ig = rp34 * d2;
                float fg = rp34 * d1;
                float og = rp12 * d4;
                float gg = (1.f - e4) * (rp12 * d3);
                float c = fg * cs[hcl * 64 + w] + ig * gg;
                cs[hcl * 64 + w] = c;
                float e5 = __expf(-2.f * clamp15(c));
                float hv2 = og * (1.f - e5) * frcp(1.f + e5);
                int ch = o0 + hcl;
                out[(((long)b * HID + ch) * HH + row) * WW + w] = hv2;
                if (row < HH - 1) hs[ch * 68 + w + 1] = hv2;
            }

            BARS(4, 512);                    // gates done -> IO may publish
        }
    } else {
        // ================= IO WARPS =================
        int iot = tid - 256;

        for (int row = 0; row < HH; row++) {
            int par = row & 1;

            if (row > 0) {
                if (iot < 8) {
                    while (ld_acquire(flags + iot) < base + row) { }
                }
                BARS(5, 256);                // spin done -> all IO may copy
                const float4* gh4 = (const float4*)&g_h[((long)par * BB + b) * HID * WW];
                for (int i = iot; i < 112 * 16; i += 256) {
                    int icl = i >> 4;
                    int ic  = icl + (icl >= o0 ? 16 : 0);
                    float4 v = gh4[ic * 16 + (i & 15)];
                    float* d = &hs[ic * 68 + (i & 15) * 4 + 1];
                    d[0] = v.x; d[1] = v.y; d[2] = v.z; d[3] = v.w;
                }
            }

            BARS(1, 512);                    // peer h staged /\ compute A done

            if (row < HH - 1) {              // prefetch next x row
                const float* xb = x + (long)b * CIN * HH * WW;
                for (int i = iot; i < 1024; i += 256) {
                    int cin = i >> 4, wq = (i & 15) * 4;
                    float4 v = *(const float4*)&xb[((long)cin * HH + row + 1) * WW + wq];
                    float* d = &xs[cin * 68 + wq + 1];
                    d[0] = v.x; d[1] = v.y; d[2] = v.z; d[3] = v.w;
                }
            }

            BARS(2, 512);                    // xs staged /\ compute B done
            BARS(4, 512);                    // gates done

            if (row < HH - 1) {
                // publish own 16 ch from smem to g_h, then release flag
                float* ghw = &g_h[((long)(par ^ 1) * BB + b) * HID * WW];
                for (int i = iot; i < 256; i += 256) {
                    int ch = o0 + (i >> 4);
                    int w4 = (i & 15) * 4;
                    const float* s = &hs[(ch - o0 + o0) * 68 + w4 + 1];
                    float4 v = make_float4(s[0], s[1], s[2], s[3]);
                    *(float4*)&ghw[ch * WW + w4] = v;
                }
                BARS(6, 256);                // IO STGs ordered before release
                if (iot == 0) st_release(flags + rank, base + row + 1);
            }
        }
    }
}

// ----------------------------------------------------------------------------
extern "C" void kernel_launch(void* const* d_in, const int* in_sizes, int n_in,
                              void* d_out, int out_size)
{
    (void)in_sizes; (void)n_in; (void)out_size;
    const float* x    = (const float*)d_in[0];
    const float* w_is = (const float*)d_in[1];
    const float* b_is = (const float*)d_in[2];
    const float* w_ss = (const float*)d_in[3];
    const float* b_ss = (const float*)d_in[4];
    float* out = (float*)d_out;

    const int scan_smem = (128 * 64 * 4 + 128 * 68 + 64 * 68 + 64 * 64 + 16 * 64) * 4; // 203776 B

    cudaFuncSetAttribute(scan_kernel, cudaFuncAttributeMaxDynamicSharedMemorySize, scan_smem);

    scan_kernel<<<BB * 8, 512, scan_smem>>>(x, w_is, b_is, w_ss, b_ss, out);
}

// round 14
// speedup vs baseline: 1.2069x; 1.0839x over previous
#include <cuda_runtime.h>
#include <cstdint>
#include <math.h>

#define BB   16
#define CIN  64
#define HH   64
#define WW   64
#define HID  128
#define OC4  512   // 4*HID

typedef unsigned long long ull;

// double-buffered h state: [par][b][ic][w]  (row0 never read -> no init needed)
__device__ float g_h[2 * BB * HID * WW];
// monotonic progress flags: [b][rank] (never reset; base read per launch)
__device__ int   g_flag[BB * 8];

// ---- packed fp32x2 helpers (SASS FFMA2 path, PTX-only) ----------------------
__device__ __forceinline__ ull pk2(float a, float b) {
    ull r; asm("mov.b64 %0, {%1,%2};" : "=l"(r) : "f"(a), "f"(b)); return r;
}
__device__ __forceinline__ ull dup2(float a) {
    ull r; asm("mov.b64 %0, {%1,%1};" : "=l"(r) : "f"(a)); return r;
}
__device__ __forceinline__ void ffma2(ull& d, ull a, ull b) {
    asm("fma.rn.f32x2 %0, %1, %2, %0;" : "+l"(d) : "l"(a), "l"(b));
}
__device__ __forceinline__ ull add2(ull a, ull b) {
    ull r; asm("add.rn.f32x2 %0, %1, %2;" : "=l"(r) : "l"(a), "l"(b)); return r;
}
__device__ __forceinline__ float lo32(ull a) {
    float x; asm("{ .reg .b32 t; mov.b64 {%0, t}, %1; }" : "=f"(x) : "l"(a)); return x;
}
__device__ __forceinline__ float hi32(ull a) {
    float x; asm("{ .reg .b32 t; mov.b64 {t, %0}, %1; }" : "=f"(x) : "l"(a)); return x;
}

// ---- fast transcendentals ----------------------------------------------------
__device__ __forceinline__ float frcp(float x) {          // MUFU.RCP
    float r; asm("rcp.approx.f32 %0, %1;" : "=f"(r) : "f"(x)); return r;
}
__device__ __forceinline__ float clamp15(float x) {
    return fminf(fmaxf(x, -15.f), 15.f);
}

// ---- scoped release/acquire flag ops ----------------------------------------
__device__ __forceinline__ void st_release(int* p, int v) {
    asm volatile("st.release.gpu.global.s32 [%0], %1;" :: "l"(p), "r"(v) : "memory");
}
__device__ __forceinline__ int ld_acquire(int* p) {
    int v;
    asm volatile("ld.acquire.gpu.global.s32 %0, [%1];" : "=r"(v) : "l"(p) : "memory");
    return v;
}

#define BARS(id, cnt) \
    asm volatile("bar.sync %0, %1;" :: "r"(id), "r"(cnt) : "memory")

#define ZST 66   // zbuf stride: even (8B-aligned ull) and 2-way-conflict only

// ----------------------------------------------------------------------------
// Warp-specialized + load-balanced fused kernel. 512 threads.
// Warps 0-7 (compute): x-conv, 52 peer-ic conv, combine, gates.
// Warps 8-15 (IO): own-16 conv, flag spin, peer-h copy, 60 peer-ic conv,
//                  xs prefetch (pipelined), zbuf2 partial, publish, release.
// ----------------------------------------------------------------------------
#define CONV_IC(ic)                                                          \
    do {                                                                     \
        const float4 wv = *(const float4*)&Wq[(ic) * 256 + l * 4];           \
        ull w0d = dup2(wv.x), w1d = dup2(wv.y), w2d = dup2(wv.z);            \
        const float* hrow = &hs[(ic) * 68 + w0];                             \
        ull A[9];                                                            \
        ulonglong2 q0 = *(const ulonglong2*)(hrow);                          \
        ulonglong2 q1 = *(const ulonglong2*)(hrow + 4);                      \
        ulonglong2 q2 = *(const ulonglong2*)(hrow + 8);                      \
        ulonglong2 q3 = *(const ulonglong2*)(hrow + 12);                     \
        A[0] = q0.x; A[1] = q0.y; A[2] = q1.x; A[3] = q1.y;                  \
        A[4] = q2.x; A[5] = q2.y; A[6] = q3.x; A[7] = q3.y;                  \
        A[8] = *(const ull*)(hrow + 16);                                     \
        _Pragma("unroll")                                                    \
        for (int k = 0; k < 8; k++) {                                        \
            ffma2(acc[k], A[k],     w0d);                                    \
            ffma2(acc[k], A[k + 1], w2d);                                    \
            ffma2(T[k],   A[k],     w1d);                                    \
        }                                                                    \
        ffma2(T[8], A[8], w1d);                                              \
    } while (0)

#define CONV_X(cin)                                                          \
    do {                                                                     \
        ull wAd = dup2(Wq[(2 * (cin))     * 256 + l * 4 + 3]);               \
        ull wBd = dup2(Wq[(2 * (cin) + 1) * 256 + l * 4 + 3]);               \
        const float* xrow = &xs[(cin) * 68 + w0];                            \
        ull A[9];                                                            \
        ulonglong2 q0 = *(const ulonglong2*)(xrow);                          \
        ulonglong2 q1 = *(const ulonglong2*)(xrow + 4);                      \
        ulonglong2 q2 = *(const ulonglong2*)(xrow + 8);                      \
        ulonglong2 q3 = *(const ulonglong2*)(xrow + 12);                     \
        A[0] = q0.x; A[1] = q0.y; A[2] = q1.x; A[3] = q1.y;                  \
        A[4] = q2.x; A[5] = q2.y; A[6] = q3.x; A[7] = q3.y;                  \
        A[8] = *(const ull*)(xrow + 16);                                     \
        _Pragma("unroll")                                                    \
        for (int k = 0; k < 8; k++) {                                        \
            ffma2(acc[k], A[k], wAd);                                        \
            ffma2(T[k],   A[k], wBd);                                        \
        }                                                                    \
        ffma2(T[8], A[8], wBd);                                              \
    } while (0)

__global__ void __launch_bounds__(512)
scan_kernel(const float* __restrict__ x,
            const float* __restrict__ w_is,
            const float* __restrict__ b_is,
            const float* __restrict__ w_ss,
            const float* __restrict__ b_ss,
            float* __restrict__ out)
{
    extern __shared__ float smem[];
    float* Wq    = smem;                    // [ic][64 l][4]      32768 floats
    float* hs    = Wq + 128 * 64 * 4;       // [128 ic][68]        8704 floats
    float* xs    = hs + 128 * 68;           // [64 cin][68]        4352 floats
    float* zbuf  = xs + 64 * 68;            // [64 l][ZST]         4224 floats
    float* zbuf2 = zbuf + 64 * ZST;         // [64 l][ZST]         4224 floats
    float* cs    = zbuf2 + 64 * ZST;        // [16 hcl][64 w]      1024 floats

    int tid  = threadIdx.x;
    int rank = blockIdx.x & 7;
    int b    = blockIdx.x >> 3;
    int o0   = rank * 16;                  // own ic range [o0, o0+16)

    int* flags = g_flag + b * 8;
    int base = *(volatile int*)(flags + rank);   // own flag: race-free

    // ---- prologue (all 512 threads) ----
    for (int i = tid; i < 128 * 64 * 4; i += 512) {
        int t = i & 3, lx = (i >> 2) & 63, ic = i >> 8;
        int ocgx = (lx >> 4) * 128 + o0 + (lx & 15);
        float v;
        if (t < 3) v = w_ss[((long)ocgx * 128 + ic) * 3 + t];
        else       v = w_is[(long)ocgx * 192 + (ic >> 1) * 3 + (ic & 1)];
        Wq[i] = v;
    }
    for (int i = tid; i < 128 * 68; i += 512) hs[i] = 0.f;
    for (int i = tid; i < 64 * 68; i += 512)  xs[i] = 0.f;
    for (int i = tid; i < 16 * 64; i += 512)  cs[i] = 0.f;
    __syncthreads();
    {   // x row 0
        const float* xb = x + (long)b * CIN * HH * WW;
        for (int i = tid; i < 1024; i += 512) {
            int cin = i >> 4, wq = (i & 15) * 4;
            float4 v = *(const float4*)&xb[((long)cin * HH + 0) * WW + wq];
            float* d = &xs[cin * 68 + wq + 1];
            d[0] = v.x; d[1] = v.y; d[2] = v.z; d[3] = v.w;
        }
    }
    __syncthreads();

    if (tid < 256) {
        // ================= COMPUTE WARPS =================
        int l  = tid & 63;
        int wb = tid >> 6;        // 0..3
        int w0 = wb * 16;
        int ocg = (l >> 4) * 128 + o0 + (l & 15);
        ull bias2 = dup2(b_ss[ocg] + b_is[ocg]);

        for (int row = 0; row < HH; row++) {
            // phase A: x-conv only (no peer data needed)
            ull acc[8], T[9];
#pragma unroll
            for (int k = 0; k < 8; k++) acc[k] = 0ull;
#pragma unroll
            for (int k = 0; k < 9; k++) T[k] = 0ull;

#pragma unroll 4
            for (int cin = 0; cin < 64; cin++) CONV_X(cin);

            BARS(1, 512);                    // peer h staged by IO

            // phase B: peer-ic slice [0, 52)
#pragma unroll 4
            for (int icl = 0; icl < 52; icl++) {
                int ic = icl + (icl >= o0 ? 16 : 0);
                CONV_IC(ic);
            }

            BARS(2, 512);                    // IO conv + zbuf2 + xs staged

            // combine: bias + own shifted tap + IO partial
#pragma unroll
            for (int k = 0; k < 8; k++) {
                ull z2 = *(const ull*)&zbuf2[l * ZST + w0 + 2 * k];
                acc[k] = add2(acc[k], add2(bias2, z2));
                acc[k] = add2(acc[k], pk2(hi32(T[k]), lo32(T[k + 1])));
            }
#pragma unroll
            for (int k = 0; k < 8; k++)
                *(ull*)&zbuf[l * ZST + w0 + 2 * k] = acc[k];

            BARS(3, 256);                    // zbuf ready (compute only)

#pragma unroll
            for (int k = 0; k < 4; k++) {
                int idx = tid + k * 256;
                int hcl = idx >> 6, w = idx & 63;
                float zi  = clamp15(zbuf[(0  + hcl) * ZST + w]);
                float zf  = clamp15(zbuf[(16 + hcl) * ZST + w]);
                float zo  = clamp15(zbuf[(32 + hcl) * ZST + w]);
                float zg2 = clamp15(zbuf[(48 + hcl) * ZST + w]);
                float e1 = __expf(-zi);
                float e2 = __expf(-zf);
                float e3 = __expf(-zo);
                float e4 = __expf(-2.f * zg2);
                float d1 = 1.f + e1, d2 = 1.f + e2, d3 = 1.f + e3, d4 = 1.f + e4;
                float p12 = d1 * d2, p34 = d3 * d4;
                float r   = frcp(p12 * p34);
                float rp34 = r * p34, rp12 = r * p12;
                float ig = rp34 * d2;
                float fg = rp34 * d1;
                float og = rp12 * d4;
                float gg = (1.f - e4) * (rp12 * d3);
                float c = fg * cs[hcl * 64 + w] + ig * gg;
                cs[hcl * 64 + w] = c;
                float e5 = __expf(-2.f * clamp15(c));
                float hv2 = og * (1.f - e5) * frcp(1.f + e5);
                int ch = o0 + hcl;
                out[(((long)b * HID + ch) * HH + row) * WW + w] = hv2;
                if (row < HH - 1) hs[ch * 68 + w + 1] = hv2;
            }

            BARS(4, 512);                    // gates done -> IO may publish
        }
    } else {
        // ================= IO WARPS =================
        int iot = tid - 256;
        int l  = iot & 63;
        int wb = iot >> 6;
        int w0 = wb * 16;

        for (int row = 0; row < HH; row++) {
            int par = row & 1;

            ull acc[8], T[9];
#pragma unroll
            for (int k = 0; k < 8; k++) acc[k] = 0ull;
#pragma unroll
            for (int k = 0; k < 9; k++) T[k] = 0ull;

            // own-16 h-conv (hs own written by gates before bar4 of prev row;
            // row 0: hs = 0 -> contributes exact zeros)
#pragma unroll 4
            for (int ic = o0; ic < o0 + 16; ic++) CONV_IC(ic);

            if (row > 0) {
                if (iot < 8) {
                    while (ld_acquire(flags + iot) < base + row) { }
                }
                BARS(5, 256);                // spin done -> all IO copy
                const float4* gh4 = (const float4*)&g_h[((long)par * BB + b) * HID * WW];
                for (int i = iot; i < 112 * 16; i += 256) {
                    int icl = i >> 4;
                    int ic  = icl + (icl >= o0 ? 16 : 0);
                    float4 v = gh4[ic * 16 + (i & 15)];
                    float* d = &hs[ic * 68 + (i & 15) * 4 + 1];
                    d[0] = v.x; d[1] = v.y; d[2] = v.z; d[3] = v.w;
                }
            }

            BARS(1, 512);                    // peer h staged /\ compute A done

            // xs prefetch: issue loads now, store after conv (pipelined)
            float4 pf[4];
            bool do_pf = (row < HH - 1);
            if (do_pf) {
                const float* xb = x + (long)b * CIN * HH * WW;
#pragma unroll
                for (int j = 0; j < 4; j++) {
                    int i = iot + j * 256;
                    int cin = i >> 4, wq = (i & 15) * 4;
                    pf[j] = *(const float4*)&xb[((long)cin * HH + row + 1) * WW + wq];
                }
            }

            // phase B slice [52, 112)
#pragma unroll 4
            for (int icl = 52; icl < 112; icl++) {
                int ic = icl + (icl >= o0 ? 16 : 0);
                CONV_IC(ic);
            }

            if (do_pf) {
#pragma unroll
                for (int j = 0; j < 4; j++) {
                    int i = iot + j * 256;
                    int cin = i >> 4, wq = (i & 15) * 4;
                    float* d = &xs[cin * 68 + wq + 1];
                    d[0] = pf[j].x; d[1] = pf[j].y; d[2] = pf[j].z; d[3] = pf[j].w;
                }
            }

            // partial z (own16 + 60 peer ic) incl. shifted tap -> zbuf2
#pragma unroll
            for (int k = 0; k < 8; k++) {
                ull z2 = add2(acc[k], pk2(hi32(T[k]), lo32(T[k + 1])));
                *(ull*)&zbuf2[l * ZST + w0 + 2 * k] = z2;
            }

            BARS(2, 512);                    // hand off to compute
            BARS(4, 512);                    // gates done

            if (row < HH - 1) {
                float* ghw = &g_h[((long)(par ^ 1) * BB + b) * HID * WW];
                int ch = o0 + (iot >> 4);
                int w4 = (iot & 15) * 4;
                const float* s = &hs[ch * 68 + w4 + 1];
                float4 v = make_float4(s[0], s[1], s[2], s[3]);
                *(float4*)&ghw[ch * WW + w4] = v;
                BARS(6, 256);                // IO STGs ordered before release
                if (iot == 0) st_release(flags + rank, base + row + 1);
            }
        }
    }
}

// ----------------------------------------------------------------------------
extern "C" void kernel_launch(void* const* d_in, const int* in_sizes, int n_in,
                              void* d_out, int out_size)
{
    (void)in_sizes; (void)n_in; (void)out_size;
    const float* x    = (const float*)d_in[0];
    const float* w_is = (const float*)d_in[1];
    const float* b_is = (const float*)d_in[2];
    const float* w_ss = (const float*)d_in[3];
    const float* b_ss = (const float*)d_in[4];
    float* out = (float*)d_out;

    const int scan_smem =
        (128 * 64 * 4 + 128 * 68 + 64 * 68 + 2 * 64 * ZST + 16 * 64) * 4; // 221184 B

    cudaFuncSetAttribute(scan_kernel, cudaFuncAttributeMaxDynamicSharedMemorySize, scan_smem);

    scan_kernel<<<BB * 8, 512, scan_smem>>>(x, w_is, b_is, w_ss, b_ss, out);
}

// round 15
// speedup vs baseline: 1.2601x; 1.0441x over previous
#include <cuda_runtime.h>
#include <cstdint>
#include <math.h>

#define BB   16
#define CIN  64
#define HH   64
#define WW   64
#define HID  128
#define OC4  512   // 4*HID

typedef unsigned long long ull;

// double-buffered h state: [par][b][ic][w]  (row0 never read -> no init needed)
__device__ float g_h[2 * BB * HID * WW];
// monotonic progress flags: [b][rank] (never reset; base read per launch)
__device__ int   g_flag[BB * 8];

// ---- packed fp32x2 helpers (SASS FFMA2 path, PTX-only) ----------------------
__device__ __forceinline__ ull pk2(float a, float b) {
    ull r; asm("mov.b64 %0, {%1,%2};" : "=l"(r) : "f"(a), "f"(b)); return r;
}
__device__ __forceinline__ ull dup2(float a) {
    ull r; asm("mov.b64 %0, {%1,%1};" : "=l"(r) : "f"(a)); return r;
}
__device__ __forceinline__ void ffma2(ull& d, ull a, ull b) {
    asm("fma.rn.f32x2 %0, %1, %2, %0;" : "+l"(d) : "l"(a), "l"(b));
}
__device__ __forceinline__ ull add2(ull a, ull b) {
    ull r; asm("add.rn.f32x2 %0, %1, %2;" : "=l"(r) : "l"(a), "l"(b)); return r;
}
__device__ __forceinline__ float lo32(ull a) {
    float x; asm("{ .reg .b32 t; mov.b64 {%0, t}, %1; }" : "=f"(x) : "l"(a)); return x;
}
__device__ __forceinline__ float hi32(ull a) {
    float x; asm("{ .reg .b32 t; mov.b64 {t, %0}, %1; }" : "=f"(x) : "l"(a)); return x;
}

// ---- fast transcendentals ----------------------------------------------------
__device__ __forceinline__ float frcp(float x) {          // MUFU.RCP
    float r; asm("rcp.approx.f32 %0, %1;" : "=f"(r) : "f"(x)); return r;
}
__device__ __forceinline__ float clamp15(float x) {
    return fminf(fmaxf(x, -15.f), 15.f);
}

// ---- scoped release/acquire flag ops ----------------------------------------
__device__ __forceinline__ void st_release(int* p, int v) {
    asm volatile("st.release.gpu.global.s32 [%0], %1;" :: "l"(p), "r"(v) : "memory");
}
__device__ __forceinline__ int ld_acquire(int* p) {
    int v;
    asm volatile("ld.acquire.gpu.global.s32 %0, [%1];" : "=r"(v) : "l"(p) : "memory");
    return v;
}

#define BARS(id, cnt) \
    asm volatile("bar.sync %0, %1;" :: "r"(id), "r"(cnt) : "memory")

#define ZST 66   // zbuf stride: even (8B-aligned ull) and 2-way-conflict only

// ----------------------------------------------------------------------------
// Warp-specialized fused kernel with ROTATED channel indexing.
// smem row icr holds global channel ic = (o0 + icr) & 127:
//   own channels -> icr [0,16), peers -> icr [16,128).
// All conv loops have compile-time bounds (no per-iter predicates).
// Warps 0-7 (compute): x-conv, icr [16,70) conv, combine; all warps: gates.
// Warps 8-15 (IO): icr [0,16)+[70,128) conv, spin/copy, xs prefetch, publish.
// ----------------------------------------------------------------------------
#define CONV_IC(icr)                                                         \
    do {                                                                     \
        const float4 wv = *(const float4*)&Wq[(icr) * 256 + l * 4];          \
        ull w0d = dup2(wv.x), w1d = dup2(wv.y), w2d = dup2(wv.z);            \
        const float* hrow = &hs[(icr) * 68 + w0];                            \
        ull A[9];                                                            \
        ulonglong2 q0 = *(const ulonglong2*)(hrow);                          \
        ulonglong2 q1 = *(const ulonglong2*)(hrow + 4);                      \
        ulonglong2 q2 = *(const ulonglong2*)(hrow + 8);                      \
        ulonglong2 q3 = *(const ulonglong2*)(hrow + 12);                     \
        A[0] = q0.x; A[1] = q0.y; A[2] = q1.x; A[3] = q1.y;                  \
        A[4] = q2.x; A[5] = q2.y; A[6] = q3.x; A[7] = q3.y;                  \
        A[8] = *(const ull*)(hrow + 16);                                     \
        _Pragma("unroll")                                                    \
        for (int k = 0; k < 8; k++) {                                        \
            ffma2(acc[k], A[k],     w0d);                                    \
            ffma2(acc[k], A[k + 1], w2d);                                    \
            ffma2(T[k],   A[k],     w1d);                                    \
        }                                                                    \
        ffma2(T[8], A[8], w1d);                                              \
    } while (0)

#define CONV_X(cin)                                                          \
    do {                                                                     \
        ull wAd = dup2(Wq[(2 * (cin))     * 256 + l * 4 + 3]);               \
        ull wBd = dup2(Wq[(2 * (cin) + 1) * 256 + l * 4 + 3]);               \
        const float* xrow = &xs[(cin) * 68 + w0];                            \
        ull A[9];                                                            \
        ulonglong2 q0 = *(const ulonglong2*)(xrow);                          \
        ulonglong2 q1 = *(const ulonglong2*)(xrow + 4);                      \
        ulonglong2 q2 = *(const ulonglong2*)(xrow + 8);                      \
        ulonglong2 q3 = *(const ulonglong2*)(xrow + 12);                     \
        A[0] = q0.x; A[1] = q0.y; A[2] = q1.x; A[3] = q1.y;                  \
        A[4] = q2.x; A[5] = q2.y; A[6] = q3.x; A[7] = q3.y;                  \
        A[8] = *(const ull*)(xrow + 16);                                     \
        _Pragma("unroll")                                                    \
        for (int k = 0; k < 8; k++) {                                        \
            ffma2(acc[k], A[k], wAd);                                        \
            ffma2(T[k],   A[k], wBd);                                        \
        }                                                                    \
        ffma2(T[8], A[8], wBd);                                              \
    } while (0)

__global__ void __launch_bounds__(512)
scan_kernel(const float* __restrict__ x,
            const float* __restrict__ w_is,
            const float* __restrict__ b_is,
            const float* __restrict__ w_ss,
            const float* __restrict__ b_ss,
            float* __restrict__ out)
{
    extern __shared__ float smem[];
    float* Wq    = smem;                    // [icr][64 l][4]     32768 floats
    float* hs    = Wq + 128 * 64 * 4;       // [128 icr][68]       8704 floats
    float* xs    = hs + 128 * 68;           // [64 cin][68]        4352 floats
    float* zbuf  = xs + 64 * 68;            // [64 l][ZST]         4224 floats
    float* zbuf2 = zbuf + 64 * ZST;         // [64 l][ZST]         4224 floats
    float* cs    = zbuf2 + 64 * ZST;        // [16 hcl][64 w]      1024 floats

    int tid  = threadIdx.x;
    int rank = blockIdx.x & 7;
    int b    = blockIdx.x >> 3;
    int o0   = rank * 16;                  // own global channels [o0, o0+16)

    int* flags = g_flag + b * 8;
    int base = *(volatile int*)(flags + rank);   // own flag: race-free

    // ---- prologue (all 512 threads) ----
    // Wq[icr].xyz = w_ss taps of global ic = (o0+icr)&127; .w = w_is slot icr.
    for (int i = tid; i < 128 * 64 * 4; i += 512) {
        int t = i & 3, lx = (i >> 2) & 63, icr = i >> 8;
        int ocgx = (lx >> 4) * 128 + o0 + (lx & 15);
        float v;
        if (t < 3) {
            int icg = (o0 + icr) & 127;
            v = w_ss[((long)ocgx * 128 + icg) * 3 + t];
        } else {
            v = w_is[(long)ocgx * 192 + (icr >> 1) * 3 + (icr & 1)];
        }
        Wq[i] = v;
    }
    for (int i = tid; i < 128 * 68; i += 512) hs[i] = 0.f;
    for (int i = tid; i < 64 * 68; i += 512)  xs[i] = 0.f;
    for (int i = tid; i < 16 * 64; i += 512)  cs[i] = 0.f;
    __syncthreads();
    {   // x row 0
        const float* xb = x + (long)b * CIN * HH * WW;
        for (int i = tid; i < 1024; i += 512) {
            int cin = i >> 4, wq = (i & 15) * 4;
            float4 v = *(const float4*)&xb[((long)cin * HH + 0) * WW + wq];
            float* d = &xs[cin * 68 + wq + 1];
            d[0] = v.x; d[1] = v.y; d[2] = v.z; d[3] = v.w;
        }
    }
    __syncthreads();

    int l  = tid & 63;            // valid for both halves (iot&63 == tid&63)
    int wb = (tid & 255) >> 6;    // 0..3
    int w0 = wb * 16;

    if (tid < 256) {
        // ================= COMPUTE WARPS =================
        int ocg = (l >> 4) * 128 + o0 + (l & 15);
        ull bias2 = dup2(b_ss[ocg] + b_is[ocg]);

        for (int row = 0; row < HH; row++) {
            // phase A: x-conv only
            ull acc[8], T[9];
#pragma unroll
            for (int k = 0; k < 8; k++) acc[k] = 0ull;
#pragma unroll
            for (int k = 0; k < 9; k++) T[k] = 0ull;

#pragma unroll 4
            for (int cin = 0; cin < 64; cin++) CONV_X(cin);

            BARS(1, 512);                    // peer h staged by IO

            // phase B: icr [16, 70) — compile-time bounds
#pragma unroll 4
            for (int icr = 16; icr < 70; icr++) CONV_IC(icr);

            BARS(2, 512);                    // IO conv + zbuf2 + xs staged

            // combine: bias + own shifted tap + IO partial
#pragma unroll
            for (int k = 0; k < 8; k++) {
                ull z2 = *(const ull*)&zbuf2[l * ZST + w0 + 2 * k];
                acc[k] = add2(acc[k], add2(bias2, z2));
                acc[k] = add2(acc[k], pk2(hi32(T[k]), lo32(T[k + 1])));
            }
#pragma unroll
            for (int k = 0; k < 8; k++)
                *(ull*)&zbuf[l * ZST + w0 + 2 * k] = acc[k];

            BARS(3, 512);                    // zbuf ready -> all gates

            // gates on ALL threads: 2 elems each
#pragma unroll
            for (int k = 0; k < 2; k++) {
                int idx = tid + k * 512;
                int hcl = idx >> 6, w = idx & 63;
                float zi  = clamp15(zbuf[(0  + hcl) * ZST + w]);
                float zf  = clamp15(zbuf[(16 + hcl) * ZST + w]);
                float zo  = clamp15(zbuf[(32 + hcl) * ZST + w]);
                float zg2 = clamp15(zbuf[(48 + hcl) * ZST + w]);
                float e1 = __expf(-zi);
                float e2 = __expf(-zf);
                float e3 = __expf(-zo);
                float e4 = __expf(-2.f * zg2);
                float d1 = 1.f + e1, d2 = 1.f + e2, d3 = 1.f + e3, d4 = 1.f + e4;
                float p12 = d1 * d2, p34 = d3 * d4;
                float r   = frcp(p12 * p34);
                float rp34 = r * p34, rp12 = r * p12;
                float ig = rp34 * d2;
                float fg = rp34 * d1;
                float og = rp12 * d4;
                float gg = (1.f - e4) * (rp12 * d3);
                float c = fg * cs[hcl * 64 + w] + ig * gg;
                cs[hcl * 64 + w] = c;
                float e5 = __expf(-2.f * clamp15(c));
                float hv2 = og * (1.f - e5) * frcp(1.f + e5);
                out[(((long)b * HID + o0 + hcl) * HH + row) * WW + w] = hv2;
                if (row < HH - 1) hs[hcl * 68 + w + 1] = hv2;   // icr = hcl
            }

            BARS(4, 512);                    // gates done -> IO may publish
        }
    } else {
        // ================= IO WARPS =================
        int iot = tid - 256;

        for (int row = 0; row < HH; row++) {
            int par = row & 1;

            ull acc[8], T[9];
#pragma unroll
            for (int k = 0; k < 8; k++) acc[k] = 0ull;
#pragma unroll
            for (int k = 0; k < 9; k++) T[k] = 0ull;

            // own-16 h-conv: icr [0,16)
#pragma unroll 4
            for (int icr = 0; icr < 16; icr++) CONV_IC(icr);

            if (row > 0) {
                if (iot < 8) {
                    while (ld_acquire(flags + iot) < base + row) { }
                }
                BARS(5, 256);                // spin done -> all IO copy
                const float4* gh4 = (const float4*)&g_h[((long)par * BB + b) * HID * WW];
                for (int i = iot; i < 112 * 16; i += 256) {
                    int j   = i >> 4;                    // 0..111
                    int icg = (o0 + 16 + j) & 127;       // global channel
                    float4 v = gh4[icg * 16 + (i & 15)];
                    float* d = &hs[(16 + j) * 68 + (i & 15) * 4 + 1];
                    d[0] = v.x; d[1] = v.y; d[2] = v.z; d[3] = v.w;
                }
            }

            BARS(1, 512);                    // peer h staged /\ compute A done

            // xs prefetch: issue loads now, store after conv (pipelined)
            float4 pf[4];
            bool do_pf = (row < HH - 1);
            if (do_pf) {
                const float* xb = x + (long)b * CIN * HH * WW;
#pragma unroll
                for (int j = 0; j < 4; j++) {
                    int i = iot + j * 256;
                    int cin = i >> 4, wq = (i & 15) * 4;
                    pf[j] = *(const float4*)&xb[((long)cin * HH + row + 1) * WW + wq];
                }
            }

            // phase B slice: icr [70, 128) — compile-time bounds
#pragma unroll 4
            for (int icr = 70; icr < 128; icr++) CONV_IC(icr);

            if (do_pf) {
#pragma unroll
                for (int j = 0; j < 4; j++) {
                    int i = iot + j * 256;
                    int cin = i >> 4, wq = (i & 15) * 4;
                    float* d = &xs[cin * 68 + wq + 1];
                    d[0] = pf[j].x; d[1] = pf[j].y; d[2] = pf[j].z; d[3] = pf[j].w;
                }
            }

            // partial z (own16 + 58 peer icr) incl. shifted tap -> zbuf2
#pragma unroll
            for (int k = 0; k < 8; k++) {
                ull z2 = add2(acc[k], pk2(hi32(T[k]), lo32(T[k + 1])));
                *(ull*)&zbuf2[l * ZST + w0 + 2 * k] = z2;
            }

            BARS(2, 512);                    // hand off to compute
            BARS(3, 512);                    // zbuf ready

            // gates on ALL threads: 2 elems each
#pragma unroll
            for (int k = 0; k < 2; k++) {
                int idx = tid + k * 512;
                int hcl = idx >> 6, w = idx & 63;
                float zi  = clamp15(zbuf[(0  + hcl) * ZST + w]);
                float zf  = clamp15(zbuf[(16 + hcl) * ZST + w]);
                float zo  = clamp15(zbuf[(32 + hcl) * ZST + w]);
                float zg2 = clamp15(zbuf[(48 + hcl) * ZST + w]);
                float e1 = __expf(-zi);
                float e2 = __expf(-zf);
                float e3 = __expf(-zo);
                float e4 = __expf(-2.f * zg2);
                float d1 = 1.f + e1, d2 = 1.f + e2, d3 = 1.f + e3, d4 = 1.f + e4;
                float p12 = d1 * d2, p34 = d3 * d4;
                float r   = frcp(p12 * p34);
                float rp34 = r * p34, rp12 = r * p12;
                float ig = rp34 * d2;
                float fg = rp34 * d1;
                float og = rp12 * d4;
                float gg = (1.f - e4) * (rp12 * d3);
                float c = fg * cs[hcl * 64 + w] + ig * gg;
                cs[hcl * 64 + w] = c;
                float e5 = __expf(-2.f * clamp15(c));
                float hv2 = og * (1.f - e5) * frcp(1.f + e5);
                out[(((long)b * HID + o0 + hcl) * HH + row) * WW + w] = hv2;
                if (row < HH - 1) hs[hcl * 68 + w + 1] = hv2;   // icr = hcl
            }

            BARS(4, 512);                    // gates done

            if (row < HH - 1) {
                // publish own 16 ch from smem (icr 0..15) to g_h, then release
                float* ghw = &g_h[((long)(par ^ 1) * BB + b) * HID * WW];
                int chl = iot >> 4;                  // 0..15
                int w4  = (iot & 15) * 4;
                const float* s = &hs[chl * 68 + w4 + 1];
                float4 v = make_float4(s[0], s[1], s[2], s[3]);
                *(float4*)&ghw[(o0 + chl) * WW + w4] = v;
                BARS(6, 256);                // IO STGs ordered before release
                if (iot == 0) st_release(flags + rank, base + row + 1);
            }
        }
    }
}

// ----------------------------------------------------------------------------
extern "C" void kernel_launch(void* const* d_in, const int* in_sizes, int n_in,
                              void* d_out, int out_size)
{
    (void)in_sizes; (void)n_in; (void)out_size;
    const float* x    = (const float*)d_in[0];
    const float* w_is = (const float*)d_in[1];
    const float* b_is = (const float*)d_in[2];
    const float* w_ss = (const float*)d_in[3];
    const float* b_ss = (const float*)d_in[4];
    float* out = (float*)d_out;

    const int scan_smem =
        (128 * 64 * 4 + 128 * 68 + 64 * 68 + 2 * 64 * ZST + 16 * 64) * 4; // 221184 B

    cudaFuncSetAttribute(scan_kernel, cudaFuncAttributeMaxDynamicSharedMemorySize, scan_smem);

    scan_kernel<<<BB * 8, 512, scan_smem>>>(x, w_is, b_is, w_ss, b_ss, out);
}

// round 16
// speedup vs baseline: 1.2833x; 1.0184x over previous
#include <cuda_runtime.h>
#include <cstdint>
#include <math.h>

#define BB   16
#define CIN  64
#define HH   64
#define WW   64
#define HID  128
#define OC4  512   // 4*HID

typedef unsigned long long ull;

// double-buffered h state: [par][b][ic][w]  (row0 never read -> no init needed)
__device__ float g_h[2 * BB * HID * WW];
// monotonic progress flags: [b][rank] (never reset; base read per launch)
__device__ int   g_flag[BB * 8];

// ---- packed fp32x2 helpers (SASS FFMA2 path, PTX-only) ----------------------
__device__ __forceinline__ ull pk2(float a, float b) {
    ull r; asm("mov.b64 %0, {%1,%2};" : "=l"(r) : "f"(a), "f"(b)); return r;
}
__device__ __forceinline__ ull dup2(float a) {
    ull r; asm("mov.b64 %0, {%1,%1};" : "=l"(r) : "f"(a)); return r;
}
__device__ __forceinline__ void ffma2(ull& d, ull a, ull b) {
    asm("fma.rn.f32x2 %0, %1, %2, %0;" : "+l"(d) : "l"(a), "l"(b));
}
__device__ __forceinline__ ull add2(ull a, ull b) {
    ull r; asm("add.rn.f32x2 %0, %1, %2;" : "=l"(r) : "l"(a), "l"(b)); return r;
}
__device__ __forceinline__ float lo32(ull a) {
    float x; asm("{ .reg .b32 t; mov.b64 {%0, t}, %1; }" : "=f"(x) : "l"(a)); return x;
}
__device__ __forceinline__ float hi32(ull a) {
    float x; asm("{ .reg .b32 t; mov.b64 {t, %0}, %1; }" : "=f"(x) : "l"(a)); return x;
}

// ---- fast transcendentals ----------------------------------------------------
__device__ __forceinline__ float frcp(float x) {          // MUFU.RCP
    float r; asm("rcp.approx.f32 %0, %1;" : "=f"(r) : "f"(x)); return r;
}
__device__ __forceinline__ float clamp15(float x) {
    return fminf(fmaxf(x, -15.f), 15.f);
}

// ---- scoped release/acquire flag ops ----------------------------------------
__device__ __forceinline__ void st_release(int* p, int v) {
    asm volatile("st.release.gpu.global.s32 [%0], %1;" :: "l"(p), "r"(v) : "memory");
}
__device__ __forceinline__ int ld_acquire(int* p) {
    int v;
    asm volatile("ld.acquire.gpu.global.s32 %0, [%1];" : "=r"(v) : "l"(p) : "memory");
    return v;
}

#define BARS(id, cnt) \
    asm volatile("bar.sync %0, %1;" :: "r"(id), "r"(cnt) : "memory")

#define ZST 66   // zbuf stride: even (8B-aligned ull) and 2-way-conflict only

// ----------------------------------------------------------------------------
// Warp-specialized fused kernel, rotated channels, compact weight layouts:
//   W01[icr][l] float2 (taps 0,1) : LDS.64, 2 wf
//   W2 [icr][l] float   (tap 2)   : LDS.32, 1 wf
//   Wx [cin][l] float2 (x taps)   : LDS.64, 2 wf  (was 8 wf via .w slots)
// zbuf is shared: IO writes partial pre-bar2, compute RMWs bar2->bar3.
// ----------------------------------------------------------------------------
#define CONV_IC(icr)                                                         \
    do {                                                                     \
        float2 wv = *(const float2*)&W01[((icr) * 64 + l) * 2];              \
        float  w2v = W2[(icr) * 64 + l];                                     \
        ull w0d = dup2(wv.x), w1d = dup2(wv.y), w2d = dup2(w2v);             \
        const float* hrow = &hs[(icr) * 68 + w0];                            \
        ull A[9];                                                            \
        ulonglong2 q0 = *(const ulonglong2*)(hrow);                          \
        ulonglong2 q1 = *(const ulonglong2*)(hrow + 4);                      \
        ulonglong2 q2 = *(const ulonglong2*)(hrow + 8);                      \
        ulonglong2 q3 = *(const ulonglong2*)(hrow + 12);                     \
        A[0] = q0.x; A[1] = q0.y; A[2] = q1.x; A[3] = q1.y;                  \
        A[4] = q2.x; A[5] = q2.y; A[6] = q3.x; A[7] = q3.y;                  \
        A[8] = *(const ull*)(hrow + 16);                                     \
        _Pragma("unroll")                                                    \
        for (int k = 0; k < 8; k++) {                                        \
            ffma2(acc[k], A[k],     w0d);                                    \
            ffma2(acc[k], A[k + 1], w2d);                                    \
            ffma2(T[k],   A[k],     w1d);                                    \
        }                                                                    \
        ffma2(T[8], A[8], w1d);                                              \
    } while (0)

#define CONV_X(cin)                                                          \
    do {                                                                     \
        float2 wv = *(const float2*)&Wx[((cin) * 64 + l) * 2];               \
        ull wAd = dup2(wv.x), wBd = dup2(wv.y);                              \
        const float* xrow = &xs[(cin) * 68 + w0];                            \
        ull A[9];                                                            \
        ulonglong2 q0 = *(const ulonglong2*)(xrow);                          \
        ulonglong2 q1 = *(const ulonglong2*)(xrow + 4);                      \
        ulonglong2 q2 = *(const ulonglong2*)(xrow + 8);                      \
        ulonglong2 q3 = *(const ulonglong2*)(xrow + 12);                     \
        A[0] = q0.x; A[1] = q0.y; A[2] = q1.x; A[3] = q1.y;                  \
        A[4] = q2.x; A[5] = q2.y; A[6] = q3.x; A[7] = q3.y;                  \
        A[8] = *(const ull*)(xrow + 16);                                     \
        _Pragma("unroll")                                                    \
        for (int k = 0; k < 8; k++) {                                        \
            ffma2(acc[k], A[k], wAd);                                        \
            ffma2(T[k],   A[k], wBd);                                        \
        }                                                                    \
        ffma2(T[8], A[8], wBd);                                              \
    } while (0)

__global__ void __launch_bounds__(512)
scan_kernel(const float* __restrict__ x,
            const float* __restrict__ w_is,
            const float* __restrict__ b_is,
            const float* __restrict__ w_ss,
            const float* __restrict__ b_ss,
            float* __restrict__ out)
{
    extern __shared__ float smem[];
    float* W01 = smem;                     // [128 icr][64 l] float2  16384 f
    float* W2  = W01 + 128 * 64 * 2;       // [128 icr][64 l] float    8192 f
    float* Wx  = W2 + 128 * 64;            // [64 cin][64 l] float2    8192 f
    float* hs  = Wx + 64 * 64 * 2;         // [128 icr][68]            8704 f
    float* xs  = hs + 128 * 68;            // [64 cin][68]             4352 f
    float* zbuf = xs + 64 * 68;            // [64 l][ZST]              4224 f
    float* cs  = zbuf + 64 * ZST;          // [16 hcl][64 w]           1024 f

    int tid  = threadIdx.x;
    int rank = blockIdx.x & 7;
    int b    = blockIdx.x >> 3;
    int o0   = rank * 16;                  // own global channels [o0, o0+16)

    int* flags = g_flag + b * 8;
    int base = *(volatile int*)(flags + rank);   // own flag: race-free

    // ---- prologue (all 512 threads) ----
    for (int i = tid; i < 128 * 64; i += 512) {
        int icr = i >> 6, lx = i & 63;
        int ocgx = (lx >> 4) * 128 + o0 + (lx & 15);
        int icg = (o0 + icr) & 127;
        const float* wp = &w_ss[((long)ocgx * 128 + icg) * 3];
        ((float2*)W01)[i] = make_float2(wp[0], wp[1]);
        W2[i] = wp[2];
    }
    for (int i = tid; i < 64 * 64; i += 512) {
        int cin = i >> 6, lx = i & 63;
        int ocgx = (lx >> 4) * 128 + o0 + (lx & 15);
        const float* wp = &w_is[(long)ocgx * 192 + cin * 3];
        ((float2*)Wx)[i] = make_float2(wp[0], wp[1]);
    }
    for (int i = tid; i < 128 * 68; i += 512) hs[i] = 0.f;
    for (int i = tid; i < 64 * 68; i += 512)  xs[i] = 0.f;
    for (int i = tid; i < 16 * 64; i += 512)  cs[i] = 0.f;
    __syncthreads();
    {   // x row 0
        const float* xb = x + (long)b * CIN * HH * WW;
        for (int i = tid; i < 1024; i += 512) {
            int cin = i >> 4, wq = (i & 15) * 4;
            float4 v = *(const float4*)&xb[((long)cin * HH + 0) * WW + wq];
            float* d = &xs[cin * 68 + wq + 1];
            d[0] = v.x; d[1] = v.y; d[2] = v.z; d[3] = v.w;
        }
    }
    __syncthreads();

    int l  = tid & 63;
    int wb = (tid & 255) >> 6;    // 0..3
    int w0 = wb * 16;

    if (tid < 256) {
        // ================= COMPUTE WARPS =================
        int ocg = (l >> 4) * 128 + o0 + (l & 15);
        ull bias2 = dup2(b_ss[ocg] + b_is[ocg]);

        for (int row = 0; row < HH; row++) {
            // phase A: x-conv only
            ull acc[8], T[9];
#pragma unroll
            for (int k = 0; k < 8; k++) acc[k] = 0ull;
#pragma unroll
            for (int k = 0; k < 9; k++) T[k] = 0ull;

#pragma unroll 4
            for (int cin = 0; cin < 64; cin++) CONV_X(cin);

            BARS(1, 512);                    // peer h staged by IO

            // phase B: icr [16, 70)
#pragma unroll 4
            for (int icr = 16; icr < 70; icr++) CONV_IC(icr);

            BARS(2, 512);                    // IO conv + zbuf partial + xs staged

            // combine: RMW zbuf (holds IO partial) += bias + own acc + tap1
#pragma unroll
            for (int k = 0; k < 8; k++) {
                ull* zp = (ull*)&zbuf[l * ZST + w0 + 2 * k];
                ull z2 = *zp;
                z2 = add2(z2, add2(acc[k], bias2));
                z2 = add2(z2, pk2(hi32(T[k]), lo32(T[k + 1])));
                *zp = z2;
            }

            BARS(3, 512);                    // zbuf ready -> all gates

            // gates on ALL threads: 2 elems each
#pragma unroll
            for (int k = 0; k < 2; k++) {
                int idx = tid + k * 512;
                int hcl = idx >> 6, w = idx & 63;
                float zi  = clamp15(zbuf[(0  + hcl) * ZST + w]);
                float zf  = clamp15(zbuf[(16 + hcl) * ZST + w]);
                float zo  = clamp15(zbuf[(32 + hcl) * ZST + w]);
                float zg2 = clamp15(zbuf[(48 + hcl) * ZST + w]);
                float e1 = __expf(-zi);
                float e2 = __expf(-zf);
                float e3 = __expf(-zo);
                float e4 = __expf(-2.f * zg2);
                float d1 = 1.f + e1, d2 = 1.f + e2, d3 = 1.f + e3, d4 = 1.f + e4;
                float p12 = d1 * d2, p34 = d3 * d4;
                float r   = frcp(p12 * p34);
                float rp34 = r * p34, rp12 = r * p12;
                float ig = rp34 * d2;
                float fg = rp34 * d1;
                float og = rp12 * d4;
                float gg = (1.f - e4) * (rp12 * d3);
                float c = fg * cs[hcl * 64 + w] + ig * gg;
                cs[hcl * 64 + w] = c;
                float e5 = __expf(-2.f * clamp15(c));
                float hv2 = og * (1.f - e5) * frcp(1.f + e5);
                out[(((long)b * HID + o0 + hcl) * HH + row) * WW + w] = hv2;
                if (row < HH - 1) hs[hcl * 68 + w + 1] = hv2;   // icr = hcl
            }

            BARS(4, 512);                    // gates done -> IO may publish
        }
    } else {
        // ================= IO WARPS =================
        int iot = tid - 256;

        for (int row = 0; row < HH; row++) {
            int par = row & 1;

            ull acc[8], T[9];
#pragma unroll
            for (int k = 0; k < 8; k++) acc[k] = 0ull;
#pragma unroll
            for (int k = 0; k < 9; k++) T[k] = 0ull;

            // own-16 h-conv: icr [0,16)
#pragma unroll 4
            for (int icr = 0; icr < 16; icr++) CONV_IC(icr);

            if (row > 0) {
                if (iot < 8) {
                    while (ld_acquire(flags + iot) < base + row) { }
                }
                BARS(5, 256);                // spin done -> all IO copy
                const float4* gh4 = (const float4*)&g_h[((long)par * BB + b) * HID * WW];
                for (int i = iot; i < 112 * 16; i += 256) {
                    int j   = i >> 4;                    // 0..111
                    int icg = (o0 + 16 + j) & 127;       // global channel
                    float4 v = gh4[icg * 16 + (i & 15)];
                    float* d = &hs[(16 + j) * 68 + (i & 15) * 4 + 1];
                    d[0] = v.x; d[1] = v.y; d[2] = v.z; d[3] = v.w;
                }
            }

            BARS(1, 512);                    // peer h staged /\ compute A done

            // xs prefetch: issue loads now, store after conv (pipelined)
            float4 pf[4];
            bool do_pf = (row < HH - 1);
            if (do_pf) {
                const float* xb = x + (long)b * CIN * HH * WW;
#pragma unroll
                for (int j = 0; j < 4; j++) {
                    int i = iot + j * 256;
                    int cin = i >> 4, wq = (i & 15) * 4;
                    pf[j] = *(const float4*)&xb[((long)cin * HH + row + 1) * WW + wq];
                }
            }

            // phase B slice: icr [70, 128)
#pragma unroll 4
            for (int icr = 70; icr < 128; icr++) CONV_IC(icr);

            if (do_pf) {
#pragma unroll
                for (int j = 0; j < 4; j++) {
                    int i = iot + j * 256;
                    int cin = i >> 4, wq = (i & 15) * 4;
                    float* d = &xs[cin * 68 + wq + 1];
                    d[0] = pf[j].x; d[1] = pf[j].y; d[2] = pf[j].z; d[3] = pf[j].w;
                }
            }

            // partial z (own16 + 58 peer icr) incl. shifted tap -> zbuf
#pragma unroll
            for (int k = 0; k < 8; k++) {
                ull z2 = add2(acc[k], pk2(hi32(T[k]), lo32(T[k + 1])));
                *(ull*)&zbuf[l * ZST + w0 + 2 * k] = z2;
            }

            BARS(2, 512);                    // hand off to compute
            BARS(3, 512);                    // zbuf ready

            // gates on ALL threads: 2 elems each
#pragma unroll
            for (int k = 0; k < 2; k++) {
                int idx = tid + k * 512;
                int hcl = idx >> 6, w = idx & 63;
                float zi  = clamp15(zbuf[(0  + hcl) * ZST + w]);
                float zf  = clamp15(zbuf[(16 + hcl) * ZST + w]);
                float zo  = clamp15(zbuf[(32 + hcl) * ZST + w]);
                float zg2 = clamp15(zbuf[(48 + hcl) * ZST + w]);
                float e1 = __expf(-zi);
                float e2 = __expf(-zf);
                float e3 = __expf(-zo);
                float e4 = __expf(-2.f * zg2);
                float d1 = 1.f + e1, d2 = 1.f + e2, d3 = 1.f + e3, d4 = 1.f + e4;
                float p12 = d1 * d2, p34 = d3 * d4;
                float r   = frcp(p12 * p34);
                float rp34 = r * p34, rp12 = r * p12;
                float ig = rp34 * d2;
                float fg = rp34 * d1;
                float og = rp12 * d4;
                float gg = (1.f - e4) * (rp12 * d3);
                float c = fg * cs[hcl * 64 + w] + ig * gg;
                cs[hcl * 64 + w] = c;
                float e5 = __expf(-2.f * clamp15(c));
                float hv2 = og * (1.f - e5) * frcp(1.f + e5);
                out[(((long)b * HID + o0 + hcl) * HH + row) * WW + w] = hv2;
                if (row < HH - 1) hs[hcl * 68 + w + 1] = hv2;   // icr = hcl
            }

            BARS(4, 512);                    // gates done

            if (row < HH - 1) {
                // publish own 16 ch from smem (icr 0..15) to g_h, then release
                float* ghw = &g_h[((long)(par ^ 1) * BB + b) * HID * WW];
                int chl = iot >> 4;                  // 0..15
                int w4  = (iot & 15) * 4;
                const float* s = &hs[chl * 68 + w4 + 1];
                float4 v = make_float4(s[0], s[1], s[2], s[3]);
                *(float4*)&ghw[(o0 + chl) * WW + w4] = v;
                BARS(6, 256);                // IO STGs ordered before release
                if (iot == 0) st_release(flags + rank, base + row + 1);
            }
        }
    }
}

// ----------------------------------------------------------------------------
extern "C" void kernel_launch(void* const* d_in, const int* in_sizes, int n_in,
                              void* d_out, int out_size)
{
    (void)in_sizes; (void)n_in; (void)out_size;
    const float* x    = (const float*)d_in[0];
    const float* w_is = (const float*)d_in[1];
    const float* b_is = (const float*)d_in[2];
    const float* w_ss = (const float*)d_in[3];
    const float* b_ss = (const float*)d_in[4];
    float* out = (float*)d_out;

    const int scan_smem =
        (128 * 64 * 2 + 128 * 64 + 64 * 64 * 2 + 128 * 68 + 64 * 68 + 64 * ZST + 16 * 64) * 4; // 204288 B

    cudaFuncSetAttribute(scan_kernel, cudaFuncAttributeMaxDynamicSharedMemorySize, scan_smem);

    scan_kernel<<<BB * 8, 512, scan_smem>>>(x, w_is, b_is, w_ss, b_ss, out);
}

// round 17
// speedup vs baseline: 1.3602x; 1.0600x over previous
#include <cuda_runtime.h>
#include <cstdint>
#include <math.h>

#define BB   16
#define CIN  64
#define HH   64
#define WW   64
#define HID  128
#define OC4  512   // 4*HID

typedef unsigned long long ull;

// double-buffered h state: [par][b][ic][w]  (row0 never read -> no init needed)
__device__ float g_h[2 * BB * HID * WW];
// monotonic progress flags: [b][rank] (never reset; base read per launch)
__device__ int   g_flag[BB * 8];

// ---- packed fp32x2 helpers (SASS FFMA2 path, PTX-only) ----------------------
__device__ __forceinline__ ull pk2(float a, float b) {
    ull r; asm("mov.b64 %0, {%1,%2};" : "=l"(r) : "f"(a), "f"(b)); return r;
}
__device__ __forceinline__ ull dup2(float a) {
    ull r; asm("mov.b64 %0, {%1,%1};" : "=l"(r) : "f"(a)); return r;
}
__device__ __forceinline__ void ffma2(ull& d, ull a, ull b) {
    asm("fma.rn.f32x2 %0, %1, %2, %0;" : "+l"(d) : "l"(a), "l"(b));
}
__device__ __forceinline__ ull add2(ull a, ull b) {
    ull r; asm("add.rn.f32x2 %0, %1, %2;" : "=l"(r) : "l"(a), "l"(b)); return r;
}
__device__ __forceinline__ float lo32(ull a) {
    float x; asm("{ .reg .b32 t; mov.b64 {%0, t}, %1; }" : "=f"(x) : "l"(a)); return x;
}
__device__ __forceinline__ float hi32(ull a) {
    float x; asm("{ .reg .b32 t; mov.b64 {t, %0}, %1; }" : "=f"(x) : "l"(a)); return x;
}

// ---- fast transcendentals ----------------------------------------------------
__device__ __forceinline__ float frcp(float x) {          // MUFU.RCP
    float r; asm("rcp.approx.f32 %0, %1;" : "=f"(r) : "f"(x)); return r;
}
__device__ __forceinline__ float clamp15(float x) {
    return fminf(fmaxf(x, -15.f), 15.f);
}

// ---- scoped release/acquire flag ops ----------------------------------------
__device__ __forceinline__ void st_release(int* p, int v) {
    asm volatile("st.release.gpu.global.s32 [%0], %1;" :: "l"(p), "r"(v) : "memory");
}
__device__ __forceinline__ int ld_acquire(int* p) {
    int v;
    asm volatile("ld.acquire.gpu.global.s32 %0, [%1];" : "=r"(v) : "l"(p) : "memory");
    return v;
}

#define BARS(id, cnt) \
    asm volatile("bar.sync %0, %1;" :: "r"(id), "r"(cnt) : "memory")

#define ZST 66   // zbuf stride: even (8B-aligned ull) and 2-way-conflict only

// ----------------------------------------------------------------------------
// Warp-specialized fused kernel, rotated channels, compact weight layouts.
// Row loop: 3 block barriers (bar1 peer-h, bar23 z-ready, bar4 row-end).
// Compute and IO both write DISJOINT z partials (zbuf2 / zbuf) pre-bar23;
// gates sum both. Gates write h directly to g_h (no IO publish step).
// ----------------------------------------------------------------------------
#define CONV_IC(icr)                                                         \
    do {                                                                     \
        float2 wv = *(const float2*)&W01[((icr) * 64 + l) * 2];              \
        float  w2v = W2[(icr) * 64 + l];                                     \
        ull w0d = dup2(wv.x), w1d = dup2(wv.y), w2d = dup2(w2v);             \
        const float* hrow = &hs[(icr) * 68 + w0];                            \
        ull A[9];                                                            \
        ulonglong2 q0 = *(const ulonglong2*)(hrow);                          \
        ulonglong2 q1 = *(const ulonglong2*)(hrow + 4);                      \
        ulonglong2 q2 = *(const ulonglong2*)(hrow + 8);                      \
        ulonglong2 q3 = *(const ulonglong2*)(hrow + 12);                     \
        A[0] = q0.x; A[1] = q0.y; A[2] = q1.x; A[3] = q1.y;                  \
        A[4] = q2.x; A[5] = q2.y; A[6] = q3.x; A[7] = q3.y;                  \
        A[8] = *(const ull*)(hrow + 16);                                     \
        _Pragma("unroll")                                                    \
        for (int k = 0; k < 8; k++) {                                        \
            ffma2(acc[k], A[k],     w0d);                                    \
            ffma2(acc[k], A[k + 1], w2d);                                    \
            ffma2(T[k],   A[k],     w1d);                                    \
        }                                                                    \
        ffma2(T[8], A[8], w1d);                                              \
    } while (0)

#define CONV_X(cin)                                                          \
    do {                                                                     \
        float2 wv = *(const float2*)&Wx[((cin) * 64 + l) * 2];               \
        ull wAd = dup2(wv.x), wBd = dup2(wv.y);                              \
        const float* xrow = &xs[(cin) * 68 + w0];                            \
        ull A[9];                                                            \
        ulonglong2 q0 = *(const ulonglong2*)(xrow);                          \
        ulonglong2 q1 = *(const ulonglong2*)(xrow + 4);                      \
        ulonglong2 q2 = *(const ulonglong2*)(xrow + 8);                      \
        ulonglong2 q3 = *(const ulonglong2*)(xrow + 12);                     \
        A[0] = q0.x; A[1] = q0.y; A[2] = q1.x; A[3] = q1.y;                  \
        A[4] = q2.x; A[5] = q2.y; A[6] = q3.x; A[7] = q3.y;                  \
        A[8] = *(const ull*)(xrow + 16);                                     \
        _Pragma("unroll")                                                    \
        for (int k = 0; k < 8; k++) {                                        \
            ffma2(acc[k], A[k], wAd);                                        \
            ffma2(T[k],   A[k], wBd);                                        \
        }                                                                    \
        ffma2(T[8], A[8], wBd);                                              \
    } while (0)

// gates on all 512 threads: 2 elems each, sum both z partials
#define GATES_BODY()                                                         \
    _Pragma("unroll")                                                        \
    for (int k = 0; k < 2; k++) {                                            \
        int idx = tid + k * 512;                                             \
        int hcl = idx >> 6, w = idx & 63;                                    \
        float zi  = clamp15(zbuf[(0  + hcl) * ZST + w] + zbuf2[(0  + hcl) * ZST + w]); \
        float zf  = clamp15(zbuf[(16 + hcl) * ZST + w] + zbuf2[(16 + hcl) * ZST + w]); \
        float zo  = clamp15(zbuf[(32 + hcl) * ZST + w] + zbuf2[(32 + hcl) * ZST + w]); \
        float zg2 = clamp15(zbuf[(48 + hcl) * ZST + w] + zbuf2[(48 + hcl) * ZST + w]); \
        float e1 = __expf(-zi);                                              \
        float e2 = __expf(-zf);                                              \
        float e3 = __expf(-zo);                                              \
        float e4 = __expf(-2.f * zg2);                                       \
        float d1 = 1.f + e1, d2 = 1.f + e2, d3 = 1.f + e3, d4 = 1.f + e4;    \
        float p12 = d1 * d2, p34 = d3 * d4;                                  \
        float r   = frcp(p12 * p34);                                         \
        float rp34 = r * p34, rp12 = r * p12;                                \
        float ig = rp34 * d2;                                                \
        float fg = rp34 * d1;                                                \
        float og = rp12 * d4;                                                \
        float gg = (1.f - e4) * (rp12 * d3);                                 \
        float c = fg * cs[hcl * 64 + w] + ig * gg;                           \
        cs[hcl * 64 + w] = c;                                                \
        float e5 = __expf(-2.f * clamp15(c));                                \
        float hv2 = og * (1.f - e5) * frcp(1.f + e5);                        \
        out[(((long)b * HID + o0 + hcl) * HH + row) * WW + w] = hv2;         \
        if (row < HH - 1) {                                                  \
            hs[hcl * 68 + w + 1] = hv2;                                      \
            ghw[(o0 + hcl) * WW + w] = hv2;                                  \
        }                                                                    \
    }

__global__ void __launch_bounds__(512)
scan_kernel(const float* __restrict__ x,
            const float* __restrict__ w_is,
            const float* __restrict__ b_is,
            const float* __restrict__ w_ss,
            const float* __restrict__ b_ss,
            float* __restrict__ out)
{
    extern __shared__ float smem[];
    float* W01 = smem;                     // [128 icr][64 l] float2  16384 f
    float* W2  = W01 + 128 * 64 * 2;       // [128 icr][64 l] float    8192 f
    float* Wx  = W2 + 128 * 64;            // [64 cin][64 l] float2    8192 f
    float* hs  = Wx + 64 * 64 * 2;         // [128 icr][68]            8704 f
    float* xs  = hs + 128 * 68;            // [64 cin][68]             4352 f
    float* zbuf  = xs + 64 * 68;           // [64 l][ZST]  (IO)        4224 f
    float* zbuf2 = zbuf + 64 * ZST;        // [64 l][ZST]  (compute)   4224 f
    float* cs  = zbuf2 + 64 * ZST;         // [16 hcl][64 w]           1024 f

    int tid  = threadIdx.x;
    int rank = blockIdx.x & 7;
    int b    = blockIdx.x >> 3;
    int o0   = rank * 16;                  // own global channels [o0, o0+16)

    int* flags = g_flag + b * 8;
    int base = *(volatile int*)(flags + rank);   // own flag: race-free

    // ---- prologue (all 512 threads) ----
    for (int i = tid; i < 128 * 64; i += 512) {
        int icr = i >> 6, lx = i & 63;
        int ocgx = (lx >> 4) * 128 + o0 + (lx & 15);
        int icg = (o0 + icr) & 127;
        const float* wp = &w_ss[((long)ocgx * 128 + icg) * 3];
        ((float2*)W01)[i] = make_float2(wp[0], wp[1]);
        W2[i] = wp[2];
    }
    for (int i = tid; i < 64 * 64; i += 512) {
        int cin = i >> 6, lx = i & 63;
        int ocgx = (lx >> 4) * 128 + o0 + (lx & 15);
        const float* wp = &w_is[(long)ocgx * 192 + cin * 3];
        ((float2*)Wx)[i] = make_float2(wp[0], wp[1]);
    }
    for (int i = tid; i < 128 * 68; i += 512) hs[i] = 0.f;
    for (int i = tid; i < 64 * 68; i += 512)  xs[i] = 0.f;
    for (int i = tid; i < 16 * 64; i += 512)  cs[i] = 0.f;
    __syncthreads();
    {   // x row 0
        const float* xb = x + (long)b * CIN * HH * WW;
        for (int i = tid; i < 1024; i += 512) {
            int cin = i >> 4, wq = (i & 15) * 4;
            float4 v = *(const float4*)&xb[((long)cin * HH + 0) * WW + wq];
            float* d = &xs[cin * 68 + wq + 1];
            d[0] = v.x; d[1] = v.y; d[2] = v.z; d[3] = v.w;
        }
    }
    __syncthreads();

    int l  = tid & 63;
    int wb = (tid & 255) >> 6;    // 0..3
    int w0 = wb * 16;

    if (tid < 256) {
        // ================= COMPUTE WARPS =================
        int ocg = (l >> 4) * 128 + o0 + (l & 15);
        ull bias2 = dup2(b_ss[ocg] + b_is[ocg]);

        for (int row = 0; row < HH; row++) {
            float* ghw = &g_h[((long)((row & 1) ^ 1) * BB + b) * HID * WW];

            // phase A: x-conv only
            ull acc[8], T[9];
#pragma unroll
            for (int k = 0; k < 8; k++) acc[k] = 0ull;
#pragma unroll
            for (int k = 0; k < 9; k++) T[k] = 0ull;

#pragma unroll 4
            for (int cin = 0; cin < 64; cin++) CONV_X(cin);

            BARS(1, 512);                    // peer h staged by IO

            // phase B: icr [16, 70)
#pragma unroll 4
            for (int icr = 16; icr < 70; icr++) CONV_IC(icr);

            // write compute partial (acc + bias + tap) to zbuf2 pre-barrier
#pragma unroll
            for (int k = 0; k < 8; k++) {
                ull z2 = add2(acc[k], bias2);
                z2 = add2(z2, pk2(hi32(T[k]), lo32(T[k + 1])));
                *(ull*)&zbuf2[l * ZST + w0 + 2 * k] = z2;
            }

            BARS(2, 512);                    // both z partials + xs staged

            GATES_BODY();

            BARS(4, 512);                    // row end: hs/g_h writes done
        }
    } else {
        // ================= IO WARPS =================
        int iot = tid - 256;

        for (int row = 0; row < HH; row++) {
            int par = row & 1;
            float* ghw = &g_h[((long)(par ^ 1) * BB + b) * HID * WW];

            ull acc[8], T[9];
#pragma unroll
            for (int k = 0; k < 8; k++) acc[k] = 0ull;
#pragma unroll
            for (int k = 0; k < 9; k++) T[k] = 0ull;

            // own-16 h-conv: icr [0,16)
#pragma unroll 4
            for (int icr = 0; icr < 16; icr++) CONV_IC(icr);

            if (row > 0) {
                if (iot < 8) {
                    while (ld_acquire(flags + iot) < base + row) { }
                }
                BARS(5, 256);                // spin done -> all IO copy
                const float4* gh4 = (const float4*)&g_h[((long)par * BB + b) * HID * WW];
                for (int i = iot; i < 112 * 16; i += 256) {
                    int j   = i >> 4;                    // 0..111
                    int icg = (o0 + 16 + j) & 127;       // global channel
                    float4 v = gh4[icg * 16 + (i & 15)];
                    float* d = &hs[(16 + j) * 68 + (i & 15) * 4 + 1];
                    d[0] = v.x; d[1] = v.y; d[2] = v.z; d[3] = v.w;
                }
            }

            BARS(1, 512);                    // peer h staged /\ compute A done

            // xs prefetch: issue loads now, store after conv (pipelined)
            float4 pf[4];
            bool do_pf = (row < HH - 1);
            if (do_pf) {
                const float* xb = x + (long)b * CIN * HH * WW;
#pragma unroll
                for (int j = 0; j < 4; j++) {
                    int i = iot + j * 256;
                    int cin = i >> 4, wq = (i & 15) * 4;
                    pf[j] = *(const float4*)&xb[((long)cin * HH + row + 1) * WW + wq];
                }
            }

            // phase B slice: icr [70, 128)
#pragma unroll 4
            for (int icr = 70; icr < 128; icr++) CONV_IC(icr);

            if (do_pf) {
#pragma unroll
                for (int j = 0; j < 4; j++) {
                    int i = iot + j * 256;
                    int cin = i >> 4, wq = (i & 15) * 4;
                    float* d = &xs[cin * 68 + wq + 1];
                    d[0] = pf[j].x; d[1] = pf[j].y; d[2] = pf[j].z; d[3] = pf[j].w;
                }
            }

            // IO partial (own16 + 58 peer icr) incl. shifted tap -> zbuf
#pragma unroll
            for (int k = 0; k < 8; k++) {
                ull z2 = add2(acc[k], pk2(hi32(T[k]), lo32(T[k + 1])));
                *(ull*)&zbuf[l * ZST + w0 + 2 * k] = z2;
            }

            BARS(2, 512);                    // both z partials staged

            GATES_BODY();

            BARS(4, 512);                    // row end: all hs/g_h writes done

            if (row < HH - 1 && iot == 0)
                st_release(flags + rank, base + row + 1);
        }
    }
}

// ----------------------------------------------------------------------------
extern "C" void kernel_launch(void* const* d_in, const int* in_sizes, int n_in,
                              void* d_out, int out_size)
{
    (void)in_sizes; (void)n_in; (void)out_size;
    const float* x    = (const float*)d_in[0];
    const float* w_is = (const float*)d_in[1];
    const float* b_is = (const float*)d_in[2];
    const float* w_ss = (const float*)d_in[3];
    const float* b_ss = (const float*)d_in[4];
    float* out = (float*)d_out;

    const int scan_smem =
        (128 * 64 * 2 + 128 * 64 + 64 * 64 * 2 + 128 * 68 + 64 * 68 + 2 * 64 * ZST + 16 * 64) * 4; // 221184 B

    cudaFuncSetAttribute(scan_kernel, cudaFuncAttributeMaxDynamicSharedMemorySize, scan_smem);

    scan_kernel<<<BB * 8, 512, scan_smem>>>(x, w_is, b_is, w_ss, b_ss, out);
}